// round 9
// baseline (speedup 1.0000x reference)
#include <cuda_runtime.h>
#include <math.h>

#define Bb   2
#define Ss   2048
#define Dd   1024
#define Hh   16
#define HDh  64
#define WINw 32
#define Mrows 4096   // B*S

// ---------------------------------------------------------------------------
// Scratch: 11 buffers of [4096 x 1024] fp32
// ---------------------------------------------------------------------------
__device__ float g_scratch[11ull * 4194304ull];

#define BM 128
#define BN 128
#define BK 16

// ---------------------------------------------------------------------------
// Core double-buffered 128x128x16 fp32 GEMM body, shared by all GEMM kernels.
// A is given as two row-blocks in K: columns [0,K1) from A1, [K1,K) from A2.
// BK divides K1, so a K-tile never straddles the boundary.
// ---------------------------------------------------------------------------
__device__ __forceinline__
void gemm_body(const float* __restrict__ A1, const float* __restrict__ A2,
               int K1, const float* __restrict__ W,
               const float* __restrict__ bias, float* __restrict__ C,
               int N, int K, int row0, int col0,
               float As[2][BK][BM], float Bs[2][BK][BN]) {
    const int tid = threadIdx.x;
    const int tr  = (tid >> 4) << 3;
    const int tc  = (tid & 15) << 3;

    const int ar0 = tid >> 2;
    const int ac0 = (tid & 3) << 2;
    const int br0 = tid >> 5;
    const int bc0 = (tid & 31) << 2;

    float acc[8][8];
#pragma unroll
    for (int i = 0; i < 8; i++)
#pragma unroll
        for (int j = 0; j < 8; j++) acc[i][j] = 0.f;

    // Preload tile 0 into buffer 0 (tile 0 is always in A1).
#pragma unroll
    for (int i = 0; i < 2; i++) {
        int r = ar0 + i * 64;
        float4 v = *(const float4*)(A1 + (size_t)(row0 + r) * K1 + ac0);
        As[0][ac0 + 0][r] = v.x;
        As[0][ac0 + 1][r] = v.y;
        As[0][ac0 + 2][r] = v.z;
        As[0][ac0 + 3][r] = v.w;
    }
#pragma unroll
    for (int i = 0; i < 2; i++) {
        int r = br0 + i * 8;
        *(float4*)&Bs[0][r][bc0] = *(const float4*)(W + (size_t)r * N + col0 + bc0);
    }
    __syncthreads();

    int cur = 0;
    for (int k0 = 0; k0 < K; k0 += BK) {
        const int knext = k0 + BK;
        float4 apre[2], bpre[2];
        if (knext < K) {
            const float* Asrc = (knext < K1) ? A1 : A2;
            const int    kc   = (knext < K1) ? knext : (knext - K1);
            const int    Ka   = (K1 < K) ? K1 : K;   // row stride of each half
#pragma unroll
            for (int i = 0; i < 2; i++) {
                int r = ar0 + i * 64;
                apre[i] = *(const float4*)(Asrc + (size_t)(row0 + r) * Ka + kc + ac0);
            }
#pragma unroll
            for (int i = 0; i < 2; i++) {
                int r = br0 + i * 8;
                bpre[i] = *(const float4*)(W + (size_t)(knext + r) * N + col0 + bc0);
            }
        }

#pragma unroll
        for (int kk = 0; kk < BK; kk++) {
            float a[8], b[8];
#pragma unroll
            for (int i = 0; i < 8; i++) a[i] = As[cur][kk][tr + i];
#pragma unroll
            for (int j = 0; j < 8; j++) b[j] = Bs[cur][kk][tc + j];
#pragma unroll
            for (int i = 0; i < 8; i++)
#pragma unroll
                for (int j = 0; j < 8; j++) acc[i][j] += a[i] * b[j];
        }

        if (knext < K) {
            const int nxt = cur ^ 1;
#pragma unroll
            for (int i = 0; i < 2; i++) {
                int r = ar0 + i * 64;
                As[nxt][ac0 + 0][r] = apre[i].x;
                As[nxt][ac0 + 1][r] = apre[i].y;
                As[nxt][ac0 + 2][r] = apre[i].z;
                As[nxt][ac0 + 3][r] = apre[i].w;
            }
#pragma unroll
            for (int i = 0; i < 2; i++) {
                int r = br0 + i * 8;
                *(float4*)&Bs[nxt][r][bc0] = bpre[i];
            }
            __syncthreads();
            cur = nxt;
        }
    }

#pragma unroll
    for (int i = 0; i < 8; i++) {
        size_t rbase = (size_t)(row0 + tr + i) * N + col0 + tc;
#pragma unroll
        for (int j = 0; j < 8; j += 4) {
            float4 o;
            o.x = acc[i][j]; o.y = acc[i][j + 1]; o.z = acc[i][j + 2]; o.w = acc[i][j + 3];
            if (bias) {
                int c = col0 + tc + j;
                o.x += bias[c]; o.y += bias[c + 1]; o.z += bias[c + 2]; o.w += bias[c + 3];
            }
            *(float4*)(C + rbase + j) = o;
        }
    }
}

// ---------------------------------------------------------------------------
// Batched QKV: blockIdx.z selects one of 6 projections. Grid (8, 32, 6).
// ---------------------------------------------------------------------------
struct QkvArgs {
    const float* W[6];
    const float* bias[6];
    float*       out[6];
};

__global__ __launch_bounds__(256)
void qkv_sgemm_kernel(const float* __restrict__ A, QkvArgs args) {
    __shared__ float As[2][BK][BM];
    __shared__ float Bs[2][BK][BN];
    const int z = blockIdx.z;
    gemm_body(A, A, Dd, args.W[z], args.bias[z], args.out[z],
              Dd, Dd, blockIdx.y * BM, blockIdx.x * BN, As, Bs);
}

// ---------------------------------------------------------------------------
// Generic GEMM (single or concat-A): C = [A1|A2] @ W + bias
// ---------------------------------------------------------------------------
__global__ __launch_bounds__(256)
void sgemm_kernel(const float* __restrict__ A1, const float* __restrict__ A2,
                  int K1, const float* __restrict__ W,
                  const float* __restrict__ bias, float* __restrict__ C,
                  int N, int K) {
    __shared__ float As[2][BK][BM];
    __shared__ float Bs[2][BK][BN];
    gemm_body(A1, A2, K1, W, bias, C, N, K,
              blockIdx.y * BM, blockIdx.x * BN, As, Bs);
}

// ---------------------------------------------------------------------------
// Flash-attention forward (causal), HD=64, 64-query tile per block.
// grid: (S/64, H, B), 256 threads. Thread t owns row r = t>>2, score/output
// columns [(t&3)*16, +16). P is exchanged within each 4-thread row-group via
// warp shuffle (the quad holds the full 64-wide P row) -- no smem staging.
// ---------------------------------------------------------------------------
#define FLASH_SMEM ((64 * 65 + 64 * 64 + 64 * 64) * 4)

__global__ void flash_fwd_kernel(const float* __restrict__ Q, const float* __restrict__ K,
                                 const float* __restrict__ V, float* __restrict__ O) {
    extern __shared__ float sm[];
    float* Qs = sm;                     // [64][65]
    float* Kt = sm + 64 * 65;           // [64(dim)][64(key)]
    float* Vs = Kt + 64 * 64;           // [64(key)][64(dim)]

    const int tid  = threadIdx.x;
    const int lane = tid & 31;
    const int qt   = gridDim.x - 1 - blockIdx.x;   // heavy tiles first
    const int h    = blockIdx.y;
    const int b    = blockIdx.z;
    const int r    = tid >> 2;
    const int c0   = (tid & 3) << 4;
    const int quad = lane & ~3;          // base lane of this thread's row-group

    const size_t base = ((size_t)b * Ss) * Dd + (size_t)h * HDh;

#pragma unroll
    for (int i = 0; i < 4; i++) {
        int f  = tid + i * 256;
        int rr = f >> 4;
        int cc = (f & 15) << 2;
        float4 v = *(const float4*)(Q + base + (size_t)(qt * 64 + rr) * Dd + cc);
        Qs[rr * 65 + cc + 0] = v.x;
        Qs[rr * 65 + cc + 1] = v.y;
        Qs[rr * 65 + cc + 2] = v.z;
        Qs[rr * 65 + cc + 3] = v.w;
    }

    const int   qidx  = qt * 64 + r;
    const float scale = 0.125f;          // 1/sqrt(64)
    float m = -1e30f, l = 0.f;
    float o[16];
#pragma unroll
    for (int i = 0; i < 16; i++) o[i] = 0.f;

    for (int kt = 0; kt <= qt; kt++) {
#pragma unroll
        for (int i = 0; i < 4; i++) {
            int f  = tid + i * 256;
            int rr = f >> 4;
            int cc = (f & 15) << 2;
            size_t g = base + (size_t)(kt * 64 + rr) * Dd + cc;
            float4 kv = *(const float4*)(K + g);
            Kt[(cc + 0) * 64 + rr] = kv.x;
            Kt[(cc + 1) * 64 + rr] = kv.y;
            Kt[(cc + 2) * 64 + rr] = kv.z;
            Kt[(cc + 3) * 64 + rr] = kv.w;
            *(float4*)(Vs + rr * 64 + cc) = *(const float4*)(V + g);
        }
        __syncthreads();

        float s[16];
#pragma unroll
        for (int c = 0; c < 16; c++) s[c] = 0.f;
#pragma unroll 4
        for (int k = 0; k < 64; k++) {
            float qv = Qs[r * 65 + k];
#pragma unroll
            for (int c = 0; c < 16; c++) s[c] += qv * Kt[k * 64 + c0 + c];
        }

        const bool diag = (kt == qt);
        float mloc = -1e30f;
#pragma unroll
        for (int c = 0; c < 16; c++) {
            float sv = s[c] * scale;
            if (diag && (kt * 64 + c0 + c) > qidx) sv = -1e30f;
            s[c] = sv;
            mloc = fmaxf(mloc, sv);
        }
        mloc = fmaxf(mloc, __shfl_xor_sync(0xffffffffu, mloc, 1));
        mloc = fmaxf(mloc, __shfl_xor_sync(0xffffffffu, mloc, 2));
        float mnew = fmaxf(m, mloc);
        float corr = __expf(m - mnew);
        float psum = 0.f;
#pragma unroll
        for (int c = 0; c < 16; c++) {
            float p = __expf(s[c] - mnew);
            s[c] = p;
            psum += p;
        }
        psum += __shfl_xor_sync(0xffffffffu, psum, 1);
        psum += __shfl_xor_sync(0xffffffffu, psum, 2);
        l = l * corr + psum;
        m = mnew;
#pragma unroll
        for (int i = 0; i < 16; i++) o[i] *= corr;

        // O += P V ; P row r lives in this thread's quad: lane quad+(c>>4)
        // holds P[r][c] in its register s[c&15].
#pragma unroll
        for (int cg = 0; cg < 4; cg++) {
            const int srcLane = quad + cg;
#pragma unroll
            for (int cl = 0; cl < 16; cl++) {
                float pv = __shfl_sync(0xffffffffu, s[cl], srcLane);
                const int c = cg * 16 + cl;
#pragma unroll
                for (int i = 0; i < 16; i++) o[i] += pv * Vs[c * 64 + c0 + i];
            }
        }
        __syncthreads();
    }

    float inv = 1.f / l;
    size_t orow = base + (size_t)qidx * Dd + c0;
#pragma unroll
    for (int i = 0; i < 16; i += 4) {
        float4 v;
        v.x = o[i] * inv; v.y = o[i + 1] * inv; v.z = o[i + 2] * inv; v.w = o[i + 3] * inv;
        *(float4*)(O + orow + i) = v;
    }
}

// ---------------------------------------------------------------------------
// Backward window attention: query q attends keys (q, q+WIN]. WIN==32: one
// warp per query, lane j owns key q+1+j. Special case q=S-1: reference sets
// all scores to 0 -> uniform softmax over full S -> mean of Vb.
// ---------------------------------------------------------------------------
__global__ __launch_bounds__(256)
void bwd_win_kernel(const float* __restrict__ Q, const float* __restrict__ K,
                    const float* __restrict__ V, float* __restrict__ O) {
    int warp = (blockIdx.x * blockDim.x + threadIdx.x) >> 5;
    int lane = threadIdx.x & 31;
    int q  = warp % Ss;
    int bh = warp / Ss;
    int h = bh % Hh, b = bh / Hh;
    size_t base = ((size_t)b * Ss) * Dd + (size_t)h * HDh;
    int d0 = lane << 1;

    if (q == Ss - 1) {
        float a0 = 0.f, a1 = 0.f;
        for (int kk = 0; kk < Ss; kk++) {
            const float* vp = V + base + (size_t)kk * Dd + d0;
            a0 += vp[0]; a1 += vp[1];
        }
        const float invS = 1.f / (float)Ss;
        *(float2*)(O + base + (size_t)q * Dd + d0) = make_float2(a0 * invS, a1 * invS);
        return;
    }

    int nk = Ss - 1 - q; if (nk > WINw) nk = WINw;
    const float* qp = Q + base + (size_t)q * Dd;
    float s = -1e30f;
    if (lane < nk) {
        const float* kp = K + base + (size_t)(q + 1 + lane) * Dd;
        float acc = 0.f;
#pragma unroll 8
        for (int d = 0; d < HDh; d++) acc += qp[d] * kp[d];
        s = acc * 0.125f;
    }
    float mx = s;
#pragma unroll
    for (int off = 16; off; off >>= 1) mx = fmaxf(mx, __shfl_xor_sync(0xffffffffu, mx, off));
    float p = (lane < nk) ? __expf(s - mx) : 0.f;
    float sum = p;
#pragma unroll
    for (int off = 16; off; off >>= 1) sum += __shfl_xor_sync(0xffffffffu, sum, off);

    float a0 = 0.f, a1 = 0.f;
    for (int j = 0; j < nk; j++) {
        float pj = __shfl_sync(0xffffffffu, p, j);
        const float* vp = V + base + (size_t)(q + 1 + j) * Dd + d0;
        a0 += pj * vp[0];
        a1 += pj * vp[1];
    }
    float inv = 1.f / sum;
    *(float2*)(O + base + (size_t)q * Dd + d0) = make_float2(a0 * inv, a1 * inv);
}

// ---------------------------------------------------------------------------
// Gate: LN(gate_pre) -> sigmoid -> fused = fwd + strength*gate*bwd
// ---------------------------------------------------------------------------
__global__ void gate_fuse_kernel(const float* __restrict__ gpre, const float* __restrict__ fwd,
                                 const float* __restrict__ bwd, const float* __restrict__ gg,
                                 const float* __restrict__ gb, const float* __restrict__ bstr,
                                 float* __restrict__ fused) {
    __shared__ float red[16];
    int row = blockIdx.x;
    size_t off = (size_t)row * Dd + (threadIdx.x << 2);
    float4 v = *(const float4*)(gpre + off);
    float sum = v.x + v.y + v.z + v.w;
    float sq  = v.x * v.x + v.y * v.y + v.z * v.z + v.w * v.w;
    int lane = threadIdx.x & 31, w = threadIdx.x >> 5;
#pragma unroll
    for (int o = 16; o; o >>= 1) {
        sum += __shfl_xor_sync(0xffffffffu, sum, o);
        sq  += __shfl_xor_sync(0xffffffffu, sq,  o);
    }
    if (lane == 0) { red[w] = sum; red[8 + w] = sq; }
    __syncthreads();
    float ts = 0.f, tq = 0.f;
#pragma unroll
    for (int i = 0; i < 8; i++) { ts += red[i]; tq += red[8 + i]; }
    float mean = ts * (1.f / Dd);
    float var  = tq * (1.f / Dd) - mean * mean;
    float rstd = rsqrtf(var + 1e-5f);
    float strength = 0.3f / (1.f + __expf(-bstr[0]));

    int c = threadIdx.x << 2;
    float4 g4 = *(const float4*)(gg + c);
    float4 b4 = *(const float4*)(gb + c);
    float4 fw = *(const float4*)(fwd + off);
    float4 bw = *(const float4*)(bwd + off);
    float4 out;
    float gx;
    gx = (v.x - mean) * rstd * g4.x + b4.x; out.x = fw.x + strength * bw.x / (1.f + __expf(-gx));
    gx = (v.y - mean) * rstd * g4.y + b4.y; out.y = fw.y + strength * bw.y / (1.f + __expf(-gx));
    gx = (v.z - mean) * rstd * g4.z + b4.z; out.z = fw.z + strength * bw.z / (1.f + __expf(-gx));
    gx = (v.w - mean) * rstd * g4.w + b4.w; out.w = fw.w + strength * bw.w / (1.f + __expf(-gx));
    *(float4*)(fused + off) = out;
}

// ---------------------------------------------------------------------------
// Final: y = LN(x + out) * g + b
// ---------------------------------------------------------------------------
__global__ void final_ln_kernel(const float* __restrict__ x, const float* __restrict__ o,
                                const float* __restrict__ gg, const float* __restrict__ gb,
                                float* __restrict__ y) {
    __shared__ float red[16];
    int row = blockIdx.x;
    size_t off = (size_t)row * Dd + (threadIdx.x << 2);
    float4 a = *(const float4*)(x + off);
    float4 c4 = *(const float4*)(o + off);
    float4 v;
    v.x = a.x + c4.x; v.y = a.y + c4.y; v.z = a.z + c4.z; v.w = a.w + c4.w;
    float sum = v.x + v.y + v.z + v.w;
    float sq  = v.x * v.x + v.y * v.y + v.z * v.z + v.w * v.w;
    int lane = threadIdx.x & 31, w = threadIdx.x >> 5;
#pragma unroll
    for (int oo = 16; oo; oo >>= 1) {
        sum += __shfl_xor_sync(0xffffffffu, sum, oo);
        sq  += __shfl_xor_sync(0xffffffffu, sq,  oo);
    }
    if (lane == 0) { red[w] = sum; red[8 + w] = sq; }
    __syncthreads();
    float ts = 0.f, tq = 0.f;
#pragma unroll
    for (int i = 0; i < 8; i++) { ts += red[i]; tq += red[8 + i]; }
    float mean = ts * (1.f / Dd);
    float var  = tq * (1.f / Dd) - mean * mean;
    float rstd = rsqrtf(var + 1e-5f);

    int c = threadIdx.x << 2;
    float4 g4 = *(const float4*)(gg + c);
    float4 b4 = *(const float4*)(gb + c);
    float4 out;
    out.x = (v.x - mean) * rstd * g4.x + b4.x;
    out.y = (v.y - mean) * rstd * g4.y + b4.y;
    out.z = (v.z - mean) * rstd * g4.z + b4.z;
    out.w = (v.w - mean) * rstd * g4.w + b4.w;
    *(float4*)(y + off) = out;
}

// ---------------------------------------------------------------------------
// Launch
// ---------------------------------------------------------------------------
extern "C" void kernel_launch(void* const* d_in, const int* in_sizes, int n_in,
                              void* d_out, int out_size) {
    const float* x      = (const float*)d_in[0];
    const float* fq_w   = (const float*)d_in[1];
    const float* fq_b   = (const float*)d_in[2];
    const float* fk_w   = (const float*)d_in[3];
    const float* fk_b   = (const float*)d_in[4];
    const float* fv_w   = (const float*)d_in[5];
    const float* fv_b   = (const float*)d_in[6];
    const float* bq_w   = (const float*)d_in[7];
    const float* bq_b   = (const float*)d_in[8];
    const float* bk_w   = (const float*)d_in[9];
    const float* bk_b   = (const float*)d_in[10];
    const float* bv_w   = (const float*)d_in[11];
    const float* bv_b   = (const float*)d_in[12];
    const float* gate_w = (const float*)d_in[13];
    const float* gate_b = (const float*)d_in[14];
    const float* gln_g  = (const float*)d_in[15];
    const float* gln_b  = (const float*)d_in[16];
    const float* bstr   = (const float*)d_in[17];
    const float* out_w  = (const float*)d_in[18];
    const float* out_b  = (const float*)d_in[19];
    const float* ln_g   = (const float*)d_in[20];
    const float* ln_b   = (const float*)d_in[21];

    float* s0 = nullptr;
    cudaGetSymbolAddress((void**)&s0, g_scratch);
    const size_t T = (size_t)Mrows * Dd;
    float* q    = s0;
    float* k    = s0 + 1 * T;
    float* v    = s0 + 2 * T;
    float* qb   = s0 + 3 * T;
    float* kb   = s0 + 4 * T;
    float* vb   = s0 + 5 * T;
    float* fwd  = s0 + 6 * T;
    float* bwd  = s0 + 7 * T;
    float* gate = s0 + 8 * T;
    float* fus  = s0 + 9 * T;
    float* ob   = s0 + 10 * T;

    cudaFuncSetAttribute(flash_fwd_kernel,
                         cudaFuncAttributeMaxDynamicSharedMemorySize, FLASH_SMEM);

    // --- 6 QKV projections in ONE launch (grid.z selects projection) ---
    QkvArgs qa;
    qa.W[0] = fq_w; qa.bias[0] = fq_b; qa.out[0] = q;
    qa.W[1] = fk_w; qa.bias[1] = fk_b; qa.out[1] = k;
    qa.W[2] = fv_w; qa.bias[2] = fv_b; qa.out[2] = v;
    qa.W[3] = bq_w; qa.bias[3] = bq_b; qa.out[3] = qb;
    qa.W[4] = bk_w; qa.bias[4] = bk_b; qa.out[4] = kb;
    qa.W[5] = bv_w; qa.bias[5] = bv_b; qa.out[5] = vb;
    qkv_sgemm_kernel<<<dim3(Dd / BN, Mrows / BM, 6), 256>>>(x, qa);

    flash_fwd_kernel<<<dim3(Ss / 64, Hh, Bb), 256, FLASH_SMEM>>>(q, k, v, fwd);
    bwd_win_kernel<<<(Bb * Hh * Ss) / 8, 256>>>(qb, kb, vb, bwd);

    dim3 gg(Dd / BN, Mrows / BM);

    // --- gate = [fwd | bwd] @ gate_w + gate_b, single K=2048 GEMM ---
    sgemm_kernel<<<gg, 256>>>(fwd, bwd, Dd, gate_w, gate_b, gate, Dd, 2 * Dd);

    gate_fuse_kernel<<<Mrows, 256>>>(gate, fwd, bwd, gln_g, gln_b, bstr, fus);

    sgemm_kernel<<<gg, 256>>>(fus, fus, Dd, out_w, out_b, ob, Dd, Dd);

    final_ln_kernel<<<Mrows, 256>>>(x, ob, ln_g, ln_b, (float*)d_out);
}

// round 15
// speedup vs baseline: 1.3740x; 1.3740x over previous
#include <cuda_runtime.h>
#include <math.h>
#include <stdint.h>

#define Bb   2
#define Ss   2048
#define Dd   1024
#define Hh   16
#define HDh  64
#define WINw 32
#define Mrows 4096   // B*S

// ---------------------------------------------------------------------------
// Scratch: 11 buffers of [4096 x 1024] fp32
// ---------------------------------------------------------------------------
__device__ float g_scratch[11ull * 4194304ull];

#define BM 128
#define BN 128
#define BKt 16
#define AST 136   // padded smem strides: bank = (idx + 8*k) % 32 -> conflict-free frags
#define BST 136

// ---------------------------------------------------------------------------
// tf32 helpers
// ---------------------------------------------------------------------------
__device__ __forceinline__ float f2tf32f(float f) {
    uint32_t u;
    asm("cvt.rna.tf32.f32 %0, %1;" : "=r"(u) : "f"(f));
    return __uint_as_float(u);
}

__device__ __forceinline__ void mma_tf32(float* d, const uint32_t* a, const uint32_t* b) {
    asm volatile(
        "mma.sync.aligned.m16n8k8.row.col.f32.tf32.tf32.f32 "
        "{%0,%1,%2,%3}, {%4,%5,%6,%7}, {%8,%9}, {%0,%1,%2,%3};\n"
        : "+f"(d[0]), "+f"(d[1]), "+f"(d[2]), "+f"(d[3])
        : "r"(a[0]), "r"(a[1]), "r"(a[2]), "r"(a[3]), "r"(b[0]), "r"(b[1]));
}

// ---------------------------------------------------------------------------
// tf32 GEMM body: C[M,N] = [A1|A2] @ W + bias. Values are rna-rounded to tf32
// at the smem-store stage; accumulation is fp32 via mma.sync.
// A in smem as [k][m] (stride AST), W as [k][n] (stride BST).
// Warp grid 2(M) x 4(N); warp tile 64x32 = 4x4 m16n8 mma tiles.
// ---------------------------------------------------------------------------
__device__ __forceinline__
void tf32_gemm_body(const float* __restrict__ A1, const float* __restrict__ A2,
                    int K1, const float* __restrict__ W,
                    const float* __restrict__ bias, float* __restrict__ C,
                    int N, int K, int row0, int col0,
                    float As[2][BKt][AST], float Bs[2][BKt][BST]) {
    const int tid    = threadIdx.x;
    const int lane   = tid & 31;
    const int wid    = tid >> 5;
    const int warp_m = wid >> 2;        // 0..1
    const int warp_n = wid & 3;         // 0..3
    const int g      = lane >> 2;       // 0..7
    const int tg     = lane & 3;        // 0..3
    const int wm     = warp_m * 64;
    const int wn     = warp_n * 32;

    // global->smem per-thread coords (2 float4 each for A and B per tile)
    const int ar0 = tid >> 2;             // + i*64
    const int ac0 = (tid & 3) << 2;
    const int br0 = tid >> 5;             // + i*8
    const int bc0 = (tid & 31) << 2;

    float acc[4][4][4];
#pragma unroll
    for (int i = 0; i < 4; i++)
#pragma unroll
        for (int j = 0; j < 4; j++)
#pragma unroll
            for (int t = 0; t < 4; t++) acc[i][j][t] = 0.f;

    // ---- preload tile 0 into buffer 0 (tile 0 is always in A1) ----
#pragma unroll
    for (int i = 0; i < 2; i++) {
        int r = ar0 + i * 64;
        float4 v = *(const float4*)(A1 + (size_t)(row0 + r) * K1 + ac0);
        As[0][ac0 + 0][r] = f2tf32f(v.x);
        As[0][ac0 + 1][r] = f2tf32f(v.y);
        As[0][ac0 + 2][r] = f2tf32f(v.z);
        As[0][ac0 + 3][r] = f2tf32f(v.w);
    }
#pragma unroll
    for (int i = 0; i < 2; i++) {
        int r = br0 + i * 8;
        float4 v = *(const float4*)(W + (size_t)r * N + col0 + bc0);
        Bs[0][r][bc0 + 0] = f2tf32f(v.x);
        Bs[0][r][bc0 + 1] = f2tf32f(v.y);
        Bs[0][r][bc0 + 2] = f2tf32f(v.z);
        Bs[0][r][bc0 + 3] = f2tf32f(v.w);
    }
    __syncthreads();

    int cur = 0;
    for (int k0 = 0; k0 < K; k0 += BKt) {
        const int knext = k0 + BKt;
        float4 apre[2], bpre[2];
        if (knext < K) {
            const float* Asrc = (knext < K1) ? A1 : A2;
            const int    kc   = (knext < K1) ? knext : (knext - K1);
            const int    Ka   = (K1 < K) ? K1 : K;
#pragma unroll
            for (int i = 0; i < 2; i++) {
                int r = ar0 + i * 64;
                apre[i] = *(const float4*)(Asrc + (size_t)(row0 + r) * Ka + kc + ac0);
            }
#pragma unroll
            for (int i = 0; i < 2; i++) {
                int r = br0 + i * 8;
                bpre[i] = *(const float4*)(W + (size_t)(knext + r) * N + col0 + bc0);
            }
        }

        // ---- compute on current buffer: 2 k8 steps ----
#pragma unroll
        for (int ks = 0; ks < 2; ks++) {
            const int kb = ks * 8;
            uint32_t afr[4][4], bfr[4][2];
#pragma unroll
            for (int i = 0; i < 4; i++) {
                const int mb = wm + i * 16;
                afr[i][0] = __float_as_uint(As[cur][kb + tg    ][mb + g    ]);
                afr[i][1] = __float_as_uint(As[cur][kb + tg    ][mb + g + 8]);
                afr[i][2] = __float_as_uint(As[cur][kb + tg + 4][mb + g    ]);
                afr[i][3] = __float_as_uint(As[cur][kb + tg + 4][mb + g + 8]);
            }
#pragma unroll
            for (int j = 0; j < 4; j++) {
                const int nb = wn + j * 8;
                bfr[j][0] = __float_as_uint(Bs[cur][kb + tg    ][nb + g]);
                bfr[j][1] = __float_as_uint(Bs[cur][kb + tg + 4][nb + g]);
            }
#pragma unroll
            for (int i = 0; i < 4; i++)
#pragma unroll
                for (int j = 0; j < 4; j++)
                    mma_tf32(acc[i][j], afr[i], bfr[j]);
        }

        if (knext < K) {
            const int nxt = cur ^ 1;
#pragma unroll
            for (int i = 0; i < 2; i++) {
                int r = ar0 + i * 64;
                As[nxt][ac0 + 0][r] = f2tf32f(apre[i].x);
                As[nxt][ac0 + 1][r] = f2tf32f(apre[i].y);
                As[nxt][ac0 + 2][r] = f2tf32f(apre[i].z);
                As[nxt][ac0 + 3][r] = f2tf32f(apre[i].w);
            }
#pragma unroll
            for (int i = 0; i < 2; i++) {
                int r = br0 + i * 8;
                Bs[nxt][r][bc0 + 0] = f2tf32f(bpre[i].x);
                Bs[nxt][r][bc0 + 1] = f2tf32f(bpre[i].y);
                Bs[nxt][r][bc0 + 2] = f2tf32f(bpre[i].z);
                Bs[nxt][r][bc0 + 3] = f2tf32f(bpre[i].w);
            }
            __syncthreads();
            cur = nxt;
        }
    }

    // ---- epilogue ----
#pragma unroll
    for (int i = 0; i < 4; i++) {
        const int mrow = row0 + wm + i * 16 + g;
#pragma unroll
        for (int j = 0; j < 4; j++) {
            const int col = col0 + wn + j * 8 + tg * 2;
            float b0v = 0.f, b1v = 0.f;
            if (bias) { b0v = bias[col]; b1v = bias[col + 1]; }
            float2 v0, v1;
            v0.x = acc[i][j][0] + b0v; v0.y = acc[i][j][1] + b1v;
            v1.x = acc[i][j][2] + b0v; v1.y = acc[i][j][3] + b1v;
            *(float2*)(C + (size_t)mrow * N + col)       = v0;
            *(float2*)(C + (size_t)(mrow + 8) * N + col) = v1;
        }
    }
}

// ---------------------------------------------------------------------------
// Batched QKV (tf32): blockIdx.z selects one of 6 projections. Grid (8,32,6).
// ---------------------------------------------------------------------------
struct QkvArgs {
    const float* W[6];
    const float* bias[6];
    float*       out[6];
};

__global__ __launch_bounds__(256)
void qkv_sgemm_kernel(const float* __restrict__ A, QkvArgs args) {
    __shared__ float As[2][BKt][AST];
    __shared__ float Bs[2][BKt][BST];
    const int z = blockIdx.z;
    tf32_gemm_body(A, A, Dd, args.W[z], args.bias[z], args.out[z],
                   Dd, Dd, blockIdx.y * BM, blockIdx.x * BN, As, Bs);
}

// ---------------------------------------------------------------------------
// Generic tf32 GEMM (single or concat-A): C = [A1|A2] @ W + bias
// ---------------------------------------------------------------------------
__global__ __launch_bounds__(256)
void sgemm_kernel(const float* __restrict__ A1, const float* __restrict__ A2,
                  int K1, const float* __restrict__ W,
                  const float* __restrict__ bias, float* __restrict__ C,
                  int N, int K) {
    __shared__ float As[2][BKt][AST];
    __shared__ float Bs[2][BKt][BST];
    tf32_gemm_body(A1, A2, K1, W, bias, C, N, K,
                   blockIdx.y * BM, blockIdx.x * BN, As, Bs);
}

// ---------------------------------------------------------------------------
// Flash-attention forward (causal), HD=64, 64-query tile per block.
// grid: (S/64, H, B), 256 threads. Thread t owns row r = t>>2, score/output
// columns [(t&3)*16, +16). P is exchanged within each 4-thread row-group via
// warp shuffle (the quad holds the full 64-wide P row) -- no smem staging.
// ---------------------------------------------------------------------------
#define FLASH_SMEM ((64 * 65 + 64 * 64 + 64 * 64) * 4)

__global__ void flash_fwd_kernel(const float* __restrict__ Q, const float* __restrict__ K,
                                 const float* __restrict__ V, float* __restrict__ O) {
    extern __shared__ float sm[];
    float* Qs = sm;                     // [64][65]
    float* Kt = sm + 64 * 65;           // [64(dim)][64(key)]
    float* Vs = Kt + 64 * 64;           // [64(key)][64(dim)]

    const int tid  = threadIdx.x;
    const int lane = tid & 31;
    const int qt   = gridDim.x - 1 - blockIdx.x;   // heavy tiles first
    const int h    = blockIdx.y;
    const int b    = blockIdx.z;
    const int r    = tid >> 2;
    const int c0   = (tid & 3) << 4;
    const int quad = lane & ~3;          // base lane of this thread's row-group

    const size_t base = ((size_t)b * Ss) * Dd + (size_t)h * HDh;

#pragma unroll
    for (int i = 0; i < 4; i++) {
        int f  = tid + i * 256;
        int rr = f >> 4;
        int cc = (f & 15) << 2;
        float4 v = *(const float4*)(Q + base + (size_t)(qt * 64 + rr) * Dd + cc);
        Qs[rr * 65 + cc + 0] = v.x;
        Qs[rr * 65 + cc + 1] = v.y;
        Qs[rr * 65 + cc + 2] = v.z;
        Qs[rr * 65 + cc + 3] = v.w;
    }

    const int   qidx  = qt * 64 + r;
    const float scale = 0.125f;          // 1/sqrt(64)
    float m = -1e30f, l = 0.f;
    float o[16];
#pragma unroll
    for (int i = 0; i < 16; i++) o[i] = 0.f;

    for (int kt = 0; kt <= qt; kt++) {
#pragma unroll
        for (int i = 0; i < 4; i++) {
            int f  = tid + i * 256;
            int rr = f >> 4;
            int cc = (f & 15) << 2;
            size_t g = base + (size_t)(kt * 64 + rr) * Dd + cc;
            float4 kv = *(const float4*)(K + g);
            Kt[(cc + 0) * 64 + rr] = kv.x;
            Kt[(cc + 1) * 64 + rr] = kv.y;
            Kt[(cc + 2) * 64 + rr] = kv.z;
            Kt[(cc + 3) * 64 + rr] = kv.w;
            *(float4*)(Vs + rr * 64 + cc) = *(const float4*)(V + g);
        }
        __syncthreads();

        float s[16];
#pragma unroll
        for (int c = 0; c < 16; c++) s[c] = 0.f;
#pragma unroll 4
        for (int k = 0; k < 64; k++) {
            float qv = Qs[r * 65 + k];
#pragma unroll
            for (int c = 0; c < 16; c++) s[c] += qv * Kt[k * 64 + c0 + c];
        }

        const bool diag = (kt == qt);
        float mloc = -1e30f;
#pragma unroll
        for (int c = 0; c < 16; c++) {
            float sv = s[c] * scale;
            if (diag && (kt * 64 + c0 + c) > qidx) sv = -1e30f;
            s[c] = sv;
            mloc = fmaxf(mloc, sv);
        }
        mloc = fmaxf(mloc, __shfl_xor_sync(0xffffffffu, mloc, 1));
        mloc = fmaxf(mloc, __shfl_xor_sync(0xffffffffu, mloc, 2));
        float mnew = fmaxf(m, mloc);
        float corr = __expf(m - mnew);
        float psum = 0.f;
#pragma unroll
        for (int c = 0; c < 16; c++) {
            float p = __expf(s[c] - mnew);
            s[c] = p;
            psum += p;
        }
        psum += __shfl_xor_sync(0xffffffffu, psum, 1);
        psum += __shfl_xor_sync(0xffffffffu, psum, 2);
        l = l * corr + psum;
        m = mnew;
#pragma unroll
        for (int i = 0; i < 16; i++) o[i] *= corr;

        // O += P V ; P row r lives in this thread's quad: lane quad+(c>>4)
        // holds P[r][c] in its register s[c&15].
#pragma unroll
        for (int cg = 0; cg < 4; cg++) {
            const int srcLane = quad + cg;
#pragma unroll
            for (int cl = 0; cl < 16; cl++) {
                float pv = __shfl_sync(0xffffffffu, s[cl], srcLane);
                const int c = cg * 16 + cl;
#pragma unroll
                for (int i = 0; i < 16; i++) o[i] += pv * Vs[c * 64 + c0 + i];
            }
        }
        __syncthreads();
    }

    float inv = 1.f / l;
    size_t orow = base + (size_t)qidx * Dd + c0;
#pragma unroll
    for (int i = 0; i < 16; i += 4) {
        float4 v;
        v.x = o[i] * inv; v.y = o[i + 1] * inv; v.z = o[i + 2] * inv; v.w = o[i + 3] * inv;
        *(float4*)(O + orow + i) = v;
    }
}

// ---------------------------------------------------------------------------
// Backward window attention: query q attends keys (q, q+WIN]. WIN==32: one
// warp per query, lane j owns key q+1+j. Special case q=S-1: reference sets
// all scores to 0 -> uniform softmax over full S -> mean of Vb.
// ---------------------------------------------------------------------------
__global__ __launch_bounds__(256)
void bwd_win_kernel(const float* __restrict__ Q, const float* __restrict__ K,
                    const float* __restrict__ V, float* __restrict__ O) {
    int warp = (blockIdx.x * blockDim.x + threadIdx.x) >> 5;
    int lane = threadIdx.x & 31;
    int q  = warp % Ss;
    int bh = warp / Ss;
    int h = bh % Hh, b = bh / Hh;
    size_t base = ((size_t)b * Ss) * Dd + (size_t)h * HDh;
    int d0 = lane << 1;

    if (q == Ss - 1) {
        float a0 = 0.f, a1 = 0.f;
        for (int kk = 0; kk < Ss; kk++) {
            const float* vp = V + base + (size_t)kk * Dd + d0;
            a0 += vp[0]; a1 += vp[1];
        }
        const float invS = 1.f / (float)Ss;
        *(float2*)(O + base + (size_t)q * Dd + d0) = make_float2(a0 * invS, a1 * invS);
        return;
    }

    int nk = Ss - 1 - q; if (nk > WINw) nk = WINw;
    const float* qp = Q + base + (size_t)q * Dd;
    float s = -1e30f;
    if (lane < nk) {
        const float* kp = K + base + (size_t)(q + 1 + lane) * Dd;
        float acc = 0.f;
#pragma unroll 8
        for (int d = 0; d < HDh; d++) acc += qp[d] * kp[d];
        s = acc * 0.125f;
    }
    float mx = s;
#pragma unroll
    for (int off = 16; off; off >>= 1) mx = fmaxf(mx, __shfl_xor_sync(0xffffffffu, mx, off));
    float p = (lane < nk) ? __expf(s - mx) : 0.f;
    float sum = p;
#pragma unroll
    for (int off = 16; off; off >>= 1) sum += __shfl_xor_sync(0xffffffffu, sum, off);

    float a0 = 0.f, a1 = 0.f;
    for (int j = 0; j < nk; j++) {
        float pj = __shfl_sync(0xffffffffu, p, j);
        const float* vp = V + base + (size_t)(q + 1 + j) * Dd + d0;
        a0 += pj * vp[0];
        a1 += pj * vp[1];
    }
    float inv = 1.f / sum;
    *(float2*)(O + base + (size_t)q * Dd + d0) = make_float2(a0 * inv, a1 * inv);
}

// ---------------------------------------------------------------------------
// Gate: LN(gate_pre) -> sigmoid -> fused = fwd + strength*gate*bwd
// ---------------------------------------------------------------------------
__global__ void gate_fuse_kernel(const float* __restrict__ gpre, const float* __restrict__ fwd,
                                 const float* __restrict__ bwd, const float* __restrict__ gg,
                                 const float* __restrict__ gb, const float* __restrict__ bstr,
                                 float* __restrict__ fused) {
    __shared__ float red[16];
    int row = blockIdx.x;
    size_t off = (size_t)row * Dd + (threadIdx.x << 2);
    float4 v = *(const float4*)(gpre + off);
    float sum = v.x + v.y + v.z + v.w;
    float sq  = v.x * v.x + v.y * v.y + v.z * v.z + v.w * v.w;
    int lane = threadIdx.x & 31, w = threadIdx.x >> 5;
#pragma unroll
    for (int o = 16; o; o >>= 1) {
        sum += __shfl_xor_sync(0xffffffffu, sum, o);
        sq  += __shfl_xor_sync(0xffffffffu, sq,  o);
    }
    if (lane == 0) { red[w] = sum; red[8 + w] = sq; }
    __syncthreads();
    float ts = 0.f, tq = 0.f;
#pragma unroll
    for (int i = 0; i < 8; i++) { ts += red[i]; tq += red[8 + i]; }
    float mean = ts * (1.f / Dd);
    float var  = tq * (1.f / Dd) - mean * mean;
    float rstd = rsqrtf(var + 1e-5f);
    float strength = 0.3f / (1.f + __expf(-bstr[0]));

    int c = threadIdx.x << 2;
    float4 g4 = *(const float4*)(gg + c);
    float4 b4 = *(const float4*)(gb + c);
    float4 fw = *(const float4*)(fwd + off);
    float4 bw = *(const float4*)(bwd + off);
    float4 out;
    float gx;
    gx = (v.x - mean) * rstd * g4.x + b4.x; out.x = fw.x + strength * bw.x / (1.f + __expf(-gx));
    gx = (v.y - mean) * rstd * g4.y + b4.y; out.y = fw.y + strength * bw.y / (1.f + __expf(-gx));
    gx = (v.z - mean) * rstd * g4.z + b4.z; out.z = fw.z + strength * bw.z / (1.f + __expf(-gx));
    gx = (v.w - mean) * rstd * g4.w + b4.w; out.w = fw.w + strength * bw.w / (1.f + __expf(-gx));
    *(float4*)(fused + off) = out;
}

// ---------------------------------------------------------------------------
// Final: y = LN(x + out) * g + b
// ---------------------------------------------------------------------------
__global__ void final_ln_kernel(const float* __restrict__ x, const float* __restrict__ o,
                                const float* __restrict__ gg, const float* __restrict__ gb,
                                float* __restrict__ y) {
    __shared__ float red[16];
    int row = blockIdx.x;
    size_t off = (size_t)row * Dd + (threadIdx.x << 2);
    float4 a = *(const float4*)(x + off);
    float4 c4 = *(const float4*)(o + off);
    float4 v;
    v.x = a.x + c4.x; v.y = a.y + c4.y; v.z = a.z + c4.z; v.w = a.w + c4.w;
    float sum = v.x + v.y + v.z + v.w;
    float sq  = v.x * v.x + v.y * v.y + v.z * v.z + v.w * v.w;
    int lane = threadIdx.x & 31, w = threadIdx.x >> 5;
#pragma unroll
    for (int oo = 16; oo; oo >>= 1) {
        sum += __shfl_xor_sync(0xffffffffu, sum, oo);
        sq  += __shfl_xor_sync(0xffffffffu, sq,  oo);
    }
    if (lane == 0) { red[w] = sum; red[8 + w] = sq; }
    __syncthreads();
    float ts = 0.f, tq = 0.f;
#pragma unroll
    for (int i = 0; i < 8; i++) { ts += red[i]; tq += red[8 + i]; }
    float mean = ts * (1.f / Dd);
    float var  = tq * (1.f / Dd) - mean * mean;
    float rstd = rsqrtf(var + 1e-5f);

    int c = threadIdx.x << 2;
    float4 g4 = *(const float4*)(gg + c);
    float4 b4 = *(const float4*)(gb + c);
    float4 out;
    out.x = (v.x - mean) * rstd * g4.x + b4.x;
    out.y = (v.y - mean) * rstd * g4.y + b4.y;
    out.z = (v.z - mean) * rstd * g4.z + b4.z;
    out.w = (v.w - mean) * rstd * g4.w + b4.w;
    *(float4*)(y + off) = out;
}

// ---------------------------------------------------------------------------
// Launch
// ---------------------------------------------------------------------------
extern "C" void kernel_launch(void* const* d_in, const int* in_sizes, int n_in,
                              void* d_out, int out_size) {
    const float* x      = (const float*)d_in[0];
    const float* fq_w   = (const float*)d_in[1];
    const float* fq_b   = (const float*)d_in[2];
    const float* fk_w   = (const float*)d_in[3];
    const float* fk_b   = (const float*)d_in[4];
    const float* fv_w   = (const float*)d_in[5];
    const float* fv_b   = (const float*)d_in[6];
    const float* bq_w   = (const float*)d_in[7];
    const float* bq_b   = (const float*)d_in[8];
    const float* bk_w   = (const float*)d_in[9];
    const float* bk_b   = (const float*)d_in[10];
    const float* bv_w   = (const float*)d_in[11];
    const float* bv_b   = (const float*)d_in[12];
    const float* gate_w = (const float*)d_in[13];
    const float* gate_b = (const float*)d_in[14];
    const float* gln_g  = (const float*)d_in[15];
    const float* gln_b  = (const float*)d_in[16];
    const float* bstr   = (const float*)d_in[17];
    const float* out_w  = (const float*)d_in[18];
    const float* out_b  = (const float*)d_in[19];
    const float* ln_g   = (const float*)d_in[20];
    const float* ln_b   = (const float*)d_in[21];

    float* s0 = nullptr;
    cudaGetSymbolAddress((void**)&s0, g_scratch);
    const size_t T = (size_t)Mrows * Dd;
    float* q    = s0;
    float* k    = s0 + 1 * T;
    float* v    = s0 + 2 * T;
    float* qb   = s0 + 3 * T;
    float* kb   = s0 + 4 * T;
    float* vb   = s0 + 5 * T;
    float* fwd  = s0 + 6 * T;
    float* bwd  = s0 + 7 * T;
    float* gate = s0 + 8 * T;
    float* fus  = s0 + 9 * T;
    float* ob   = s0 + 10 * T;

    cudaFuncSetAttribute(flash_fwd_kernel,
                         cudaFuncAttributeMaxDynamicSharedMemorySize, FLASH_SMEM);

    // --- 6 QKV projections in ONE launch (grid.z selects projection) ---
    QkvArgs qa;
    qa.W[0] = fq_w; qa.bias[0] = fq_b; qa.out[0] = q;
    qa.W[1] = fk_w; qa.bias[1] = fk_b; qa.out[1] = k;
    qa.W[2] = fv_w; qa.bias[2] = fv_b; qa.out[2] = v;
    qa.W[3] = bq_w; qa.bias[3] = bq_b; qa.out[3] = qb;
    qa.W[4] = bk_w; qa.bias[4] = bk_b; qa.out[4] = kb;
    qa.W[5] = bv_w; qa.bias[5] = bv_b; qa.out[5] = vb;
    qkv_sgemm_kernel<<<dim3(Dd / BN, Mrows / BM, 6), 256>>>(x, qa);

    flash_fwd_kernel<<<dim3(Ss / 64, Hh, Bb), 256, FLASH_SMEM>>>(q, k, v, fwd);
    bwd_win_kernel<<<(Bb * Hh * Ss) / 8, 256>>>(qb, kb, vb, bwd);

    dim3 gg(Dd / BN, Mrows / BM);

    // --- gate = [fwd | bwd] @ gate_w + gate_b, single K=2048 tf32 GEMM ---
    sgemm_kernel<<<gg, 256>>>(fwd, bwd, Dd, gate_w, gate_b, gate, Dd, 2 * Dd);

    gate_fuse_kernel<<<Mrows, 256>>>(gate, fwd, bwd, gln_g, gln_b, bstr, fus);

    sgemm_kernel<<<gg, 256>>>(fus, fus, Dd, out_w, out_b, ob, Dd, Dd);

    final_ln_kernel<<<Mrows, 256>>>(x, ob, ln_g, ln_b, (float*)d_out);
}

// round 16
// speedup vs baseline: 3.3950x; 2.4709x over previous
#include <cuda_runtime.h>
#include <math.h>
#include <stdint.h>

#define Bb   2
#define Ss   2048
#define Dd   1024
#define Hh   16
#define HDh  64
#define WINw 32
#define Mrows 4096   // B*S

__device__ float g_scratch[11ull * 4194304ull];

#define BM 128
#define BN 128
#define BKt 16
#define AST 136
#define BST 136

// ---------------------------------------------------------------------------
// tf32 helpers (fragment layouts hardware-validated in R15)
// ---------------------------------------------------------------------------
__device__ __forceinline__ float f2tf32f(float f) {
    uint32_t u;
    asm("cvt.rna.tf32.f32 %0, %1;" : "=r"(u) : "f"(f));
    return __uint_as_float(u);
}

__device__ __forceinline__ void mma_tf32(float* d, const uint32_t* a, const uint32_t* b) {
    asm volatile(
        "mma.sync.aligned.m16n8k8.row.col.f32.tf32.tf32.f32 "
        "{%0,%1,%2,%3}, {%4,%5,%6,%7}, {%8,%9}, {%0,%1,%2,%3};\n"
        : "+f"(d[0]), "+f"(d[1]), "+f"(d[2]), "+f"(d[3])
        : "r"(a[0]), "r"(a[1]), "r"(a[2]), "r"(a[3]), "r"(b[0]), "r"(b[1]));
}

// ---------------------------------------------------------------------------
// tf32 GEMM body (unchanged from R15-passing kernel)
// ---------------------------------------------------------------------------
__device__ __forceinline__
void tf32_gemm_body(const float* __restrict__ A1, const float* __restrict__ A2,
                    int K1, const float* __restrict__ W,
                    const float* __restrict__ bias, float* __restrict__ C,
                    int N, int K, int row0, int col0,
                    float As[2][BKt][AST], float Bs[2][BKt][BST]) {
    const int tid    = threadIdx.x;
    const int lane   = tid & 31;
    const int wid    = tid >> 5;
    const int warp_m = wid >> 2;
    const int warp_n = wid & 3;
    const int g      = lane >> 2;
    const int tg     = lane & 3;
    const int wm     = warp_m * 64;
    const int wn     = warp_n * 32;

    const int ar0 = tid >> 2;
    const int ac0 = (tid & 3) << 2;
    const int br0 = tid >> 5;
    const int bc0 = (tid & 31) << 2;

    float acc[4][4][4];
#pragma unroll
    for (int i = 0; i < 4; i++)
#pragma unroll
        for (int j = 0; j < 4; j++)
#pragma unroll
            for (int t = 0; t < 4; t++) acc[i][j][t] = 0.f;

#pragma unroll
    for (int i = 0; i < 2; i++) {
        int r = ar0 + i * 64;
        float4 v = *(const float4*)(A1 + (size_t)(row0 + r) * K1 + ac0);
        As[0][ac0 + 0][r] = f2tf32f(v.x);
        As[0][ac0 + 1][r] = f2tf32f(v.y);
        As[0][ac0 + 2][r] = f2tf32f(v.z);
        As[0][ac0 + 3][r] = f2tf32f(v.w);
    }
#pragma unroll
    for (int i = 0; i < 2; i++) {
        int r = br0 + i * 8;
        float4 v = *(const float4*)(W + (size_t)r * N + col0 + bc0);
        Bs[0][r][bc0 + 0] = f2tf32f(v.x);
        Bs[0][r][bc0 + 1] = f2tf32f(v.y);
        Bs[0][r][bc0 + 2] = f2tf32f(v.z);
        Bs[0][r][bc0 + 3] = f2tf32f(v.w);
    }
    __syncthreads();

    int cur = 0;
    for (int k0 = 0; k0 < K; k0 += BKt) {
        const int knext = k0 + BKt;
        float4 apre[2], bpre[2];
        if (knext < K) {
            const float* Asrc = (knext < K1) ? A1 : A2;
            const int    kc   = (knext < K1) ? knext : (knext - K1);
            const int    Ka   = (K1 < K) ? K1 : K;
#pragma unroll
            for (int i = 0; i < 2; i++) {
                int r = ar0 + i * 64;
                apre[i] = *(const float4*)(Asrc + (size_t)(row0 + r) * Ka + kc + ac0);
            }
#pragma unroll
            for (int i = 0; i < 2; i++) {
                int r = br0 + i * 8;
                bpre[i] = *(const float4*)(W + (size_t)(knext + r) * N + col0 + bc0);
            }
        }

#pragma unroll
        for (int ks = 0; ks < 2; ks++) {
            const int kb = ks * 8;
            uint32_t afr[4][4], bfr[4][2];
#pragma unroll
            for (int i = 0; i < 4; i++) {
                const int mb = wm + i * 16;
                afr[i][0] = __float_as_uint(As[cur][kb + tg    ][mb + g    ]);
                afr[i][1] = __float_as_uint(As[cur][kb + tg    ][mb + g + 8]);
                afr[i][2] = __float_as_uint(As[cur][kb + tg + 4][mb + g    ]);
                afr[i][3] = __float_as_uint(As[cur][kb + tg + 4][mb + g + 8]);
            }
#pragma unroll
            for (int j = 0; j < 4; j++) {
                const int nb = wn + j * 8;
                bfr[j][0] = __float_as_uint(Bs[cur][kb + tg    ][nb + g]);
                bfr[j][1] = __float_as_uint(Bs[cur][kb + tg + 4][nb + g]);
            }
#pragma unroll
            for (int i = 0; i < 4; i++)
#pragma unroll
                for (int j = 0; j < 4; j++)
                    mma_tf32(acc[i][j], afr[i], bfr[j]);
        }

        if (knext < K) {
            const int nxt = cur ^ 1;
#pragma unroll
            for (int i = 0; i < 2; i++) {
                int r = ar0 + i * 64;
                As[nxt][ac0 + 0][r] = f2tf32f(apre[i].x);
                As[nxt][ac0 + 1][r] = f2tf32f(apre[i].y);
                As[nxt][ac0 + 2][r] = f2tf32f(apre[i].z);
                As[nxt][ac0 + 3][r] = f2tf32f(apre[i].w);
            }
#pragma unroll
            for (int i = 0; i < 2; i++) {
                int r = br0 + i * 8;
                Bs[nxt][r][bc0 + 0] = f2tf32f(bpre[i].x);
                Bs[nxt][r][bc0 + 1] = f2tf32f(bpre[i].y);
                Bs[nxt][r][bc0 + 2] = f2tf32f(bpre[i].z);
                Bs[nxt][r][bc0 + 3] = f2tf32f(bpre[i].w);
            }
            __syncthreads();
            cur = nxt;
        }
    }

#pragma unroll
    for (int i = 0; i < 4; i++) {
        const int mrow = row0 + wm + i * 16 + g;
#pragma unroll
        for (int j = 0; j < 4; j++) {
            const int col = col0 + wn + j * 8 + tg * 2;
            float b0v = 0.f, b1v = 0.f;
            if (bias) { b0v = bias[col]; b1v = bias[col + 1]; }
            float2 v0, v1;
            v0.x = acc[i][j][0] + b0v; v0.y = acc[i][j][1] + b1v;
            v1.x = acc[i][j][2] + b0v; v1.y = acc[i][j][3] + b1v;
            *(float2*)(C + (size_t)mrow * N + col)       = v0;
            *(float2*)(C + (size_t)(mrow + 8) * N + col) = v1;
        }
    }
}

struct QkvArgs {
    const float* W[6];
    const float* bias[6];
    float*       out[6];
};

__global__ __launch_bounds__(256)
void qkv_sgemm_kernel(const float* __restrict__ A, QkvArgs args) {
    __shared__ float As[2][BKt][AST];
    __shared__ float Bs[2][BKt][BST];
    const int z = blockIdx.z;
    tf32_gemm_body(A, A, Dd, args.W[z], args.bias[z], args.out[z],
                   Dd, Dd, blockIdx.y * BM, blockIdx.x * BN, As, Bs);
}

__global__ __launch_bounds__(256)
void sgemm_kernel(const float* __restrict__ A1, const float* __restrict__ A2,
                  int K1, const float* __restrict__ W,
                  const float* __restrict__ bias, float* __restrict__ C,
                  int N, int K) {
    __shared__ float As[2][BKt][AST];
    __shared__ float Bs[2][BKt][BST];
    tf32_gemm_body(A1, A2, K1, W, bias, C, N, K,
                   blockIdx.y * BM, blockIdx.x * BN, As, Bs);
}

// ---------------------------------------------------------------------------
// Flash-attention forward (causal) with tf32 mma for QK^T and P.V.
// 128 threads = 4 warps; warp w owns query rows [16w, 16w+16).
// S/O accumulators in m16n8 fragment layout: thread (g,tg) holds rows g,g+8,
// cols j*8 + 2tg,+1 -> softmax is warp(quad)-local.
// Smem stride 72 (== 8 mod 32) -> all fragment LDS conflict-free.
// ---------------------------------------------------------------------------
#define FP 72
#define FLASH_SMEM (3 * 64 * FP * 4)

__global__ void flash_fwd_kernel(const float* __restrict__ Q, const float* __restrict__ K,
                                 const float* __restrict__ V, float* __restrict__ O) {
    extern __shared__ float sm[];
    float* Qs = sm;                 // [d][q]   64 x FP
    float* Kt = sm + 64 * FP;       // [d][key] 64 x FP
    float* Vs = sm + 2 * 64 * FP;   // [key][d] 64 x FP

    const int tid  = threadIdx.x;
    const int lane = tid & 31;
    const int w    = tid >> 5;            // 0..3
    const int g    = lane >> 2;           // 0..7
    const int tg   = lane & 3;            // 0..3
    const int quad = lane & ~3;
    const int wm   = w * 16;              // warp query-row base in tile

    const int qt = gridDim.x - 1 - blockIdx.x;   // heavy tiles first
    const int h  = blockIdx.y;
    const int b  = blockIdx.z;
    const size_t base = ((size_t)b * Ss) * Dd + (size_t)h * HDh;

    // ---- load Q tile transposed into Qs[d][q], tf32-rounded ----
#pragma unroll
    for (int i = 0; i < 8; i++) {
        int f  = tid + i * 128;           // float4 index 0..1023
        int rr = f >> 4;                  // q row
        int cc = (f & 15) << 2;           // d col
        float4 v = *(const float4*)(Q + base + (size_t)(qt * 64 + rr) * Dd + cc);
        Qs[(cc + 0) * FP + rr] = f2tf32f(v.x);
        Qs[(cc + 1) * FP + rr] = f2tf32f(v.y);
        Qs[(cc + 2) * FP + rr] = f2tf32f(v.z);
        Qs[(cc + 3) * FP + rr] = f2tf32f(v.w);
    }
    __syncthreads();

    // ---- preload Q A-fragments (loop-invariant): 8 k8-steps x 4 regs ----
    uint32_t qf[8][4];
#pragma unroll
    for (int kd = 0; kd < 8; kd++) {
        qf[kd][0] = __float_as_uint(Qs[(8 * kd + tg    ) * FP + wm + g    ]);
        qf[kd][1] = __float_as_uint(Qs[(8 * kd + tg    ) * FP + wm + g + 8]);
        qf[kd][2] = __float_as_uint(Qs[(8 * kd + tg + 4) * FP + wm + g    ]);
        qf[kd][3] = __float_as_uint(Qs[(8 * kd + tg + 4) * FP + wm + g + 8]);
    }

    const int   rowg0 = qt * 64 + wm + g;   // global query row for c0,c1
    const int   rowg8 = rowg0 + 8;          // for c2,c3
    const float scale = 0.125f;

    float rm0 = -1e30f, rm8 = -1e30f, rl0 = 0.f, rl8 = 0.f;
    float oacc[8][4];
#pragma unroll
    for (int j = 0; j < 8; j++)
#pragma unroll
        for (int t = 0; t < 4; t++) oacc[j][t] = 0.f;

    for (int kt = 0; kt <= qt; kt++) {
        // ---- cooperative load of K (transposed) and V tiles, tf32-rounded ----
#pragma unroll
        for (int i = 0; i < 8; i++) {
            int f  = tid + i * 128;
            int rr = f >> 4;              // key row
            int cc = (f & 15) << 2;       // d col
            size_t gaddr = base + (size_t)(kt * 64 + rr) * Dd + cc;
            float4 kv = *(const float4*)(K + gaddr);
            Kt[(cc + 0) * FP + rr] = f2tf32f(kv.x);
            Kt[(cc + 1) * FP + rr] = f2tf32f(kv.y);
            Kt[(cc + 2) * FP + rr] = f2tf32f(kv.z);
            Kt[(cc + 3) * FP + rr] = f2tf32f(kv.w);
            float4 vv = *(const float4*)(V + gaddr);
            float4 vr;
            vr.x = f2tf32f(vv.x); vr.y = f2tf32f(vv.y);
            vr.z = f2tf32f(vv.z); vr.w = f2tf32f(vv.w);
            *(float4*)(Vs + rr * FP + cc) = vr;
        }
        __syncthreads();

        // ---- S = Q K^T : 8 k8-steps x 8 n8-tiles of mma ----
        float sacc[8][4];
#pragma unroll
        for (int j = 0; j < 8; j++)
#pragma unroll
            for (int t = 0; t < 4; t++) sacc[j][t] = 0.f;
#pragma unroll
        for (int kd = 0; kd < 8; kd++) {
#pragma unroll
            for (int j = 0; j < 8; j++) {
                uint32_t bf[2];
                bf[0] = __float_as_uint(Kt[(8 * kd + tg    ) * FP + 8 * j + g]);
                bf[1] = __float_as_uint(Kt[(8 * kd + tg + 4) * FP + 8 * j + g]);
                mma_tf32(sacc[j], qf[kd], bf);
            }
        }

        // ---- scale + causal mask (diag tile only) ----
        const bool diag = (kt == qt);
#pragma unroll
        for (int j = 0; j < 8; j++) {
            int col = kt * 64 + 8 * j + 2 * tg;
            sacc[j][0] *= scale; sacc[j][1] *= scale;
            sacc[j][2] *= scale; sacc[j][3] *= scale;
            if (diag) {
                if (col     > rowg0) sacc[j][0] = -1e30f;
                if (col + 1 > rowg0) sacc[j][1] = -1e30f;
                if (col     > rowg8) sacc[j][2] = -1e30f;
                if (col + 1 > rowg8) sacc[j][3] = -1e30f;
            }
        }

        // ---- online softmax (rows g and g+8; quad-local reduction) ----
        float mx0 = -1e30f, mx8 = -1e30f;
#pragma unroll
        for (int j = 0; j < 8; j++) {
            mx0 = fmaxf(mx0, fmaxf(sacc[j][0], sacc[j][1]));
            mx8 = fmaxf(mx8, fmaxf(sacc[j][2], sacc[j][3]));
        }
        mx0 = fmaxf(mx0, __shfl_xor_sync(0xffffffffu, mx0, 1));
        mx0 = fmaxf(mx0, __shfl_xor_sync(0xffffffffu, mx0, 2));
        mx8 = fmaxf(mx8, __shfl_xor_sync(0xffffffffu, mx8, 1));
        mx8 = fmaxf(mx8, __shfl_xor_sync(0xffffffffu, mx8, 2));

        float mnew0 = fmaxf(rm0, mx0), mnew8 = fmaxf(rm8, mx8);
        float corr0 = __expf(rm0 - mnew0), corr8 = __expf(rm8 - mnew8);

        float sum0 = 0.f, sum8 = 0.f;
#pragma unroll
        for (int j = 0; j < 8; j++) {
            sacc[j][0] = __expf(sacc[j][0] - mnew0);
            sacc[j][1] = __expf(sacc[j][1] - mnew0);
            sacc[j][2] = __expf(sacc[j][2] - mnew8);
            sacc[j][3] = __expf(sacc[j][3] - mnew8);
            sum0 += sacc[j][0] + sacc[j][1];
            sum8 += sacc[j][2] + sacc[j][3];
        }
        sum0 += __shfl_xor_sync(0xffffffffu, sum0, 1);
        sum0 += __shfl_xor_sync(0xffffffffu, sum0, 2);
        sum8 += __shfl_xor_sync(0xffffffffu, sum8, 1);
        sum8 += __shfl_xor_sync(0xffffffffu, sum8, 2);

        rl0 = rl0 * corr0 + sum0;  rm0 = mnew0;
        rl8 = rl8 * corr8 + sum8;  rm8 = mnew8;
#pragma unroll
        for (int j = 0; j < 8; j++) {
            oacc[j][0] *= corr0; oacc[j][1] *= corr0;
            oacc[j][2] *= corr8; oacc[j][3] *= corr8;
        }

        // ---- O += P V : remap P accumulator -> A-fragments via quad shuffles ----
#pragma unroll
        for (int ks = 0; ks < 8; ks++) {
            const int srcA = quad + (tg >> 1);       // cols 2tg' = tg
            const int srcB = srcA + 2;               // cols 2tg' = tg+4
            float p0 = __shfl_sync(0xffffffffu, sacc[ks][0], srcA);
            float p1 = __shfl_sync(0xffffffffu, sacc[ks][1], srcA);
            float p2 = __shfl_sync(0xffffffffu, sacc[ks][2], srcA);
            float p3 = __shfl_sync(0xffffffffu, sacc[ks][3], srcA);
            float q0 = __shfl_sync(0xffffffffu, sacc[ks][0], srcB);
            float q1 = __shfl_sync(0xffffffffu, sacc[ks][1], srcB);
            float q2 = __shfl_sync(0xffffffffu, sacc[ks][2], srcB);
            float q3 = __shfl_sync(0xffffffffu, sacc[ks][3], srcB);
            uint32_t af[4];
            af[0] = __float_as_uint(f2tf32f((tg & 1) ? p1 : p0));   // P(g,    8ks+tg)
            af[1] = __float_as_uint(f2tf32f((tg & 1) ? p3 : p2));   // P(g+8,  8ks+tg)
            af[2] = __float_as_uint(f2tf32f((tg & 1) ? q1 : q0));   // P(g,    8ks+tg+4)
            af[3] = __float_as_uint(f2tf32f((tg & 1) ? q3 : q2));   // P(g+8,  8ks+tg+4)
#pragma unroll
            for (int j = 0; j < 8; j++) {
                uint32_t bf[2];
                bf[0] = __float_as_uint(Vs[(8 * ks + tg    ) * FP + 8 * j + g]);
                bf[1] = __float_as_uint(Vs[(8 * ks + tg + 4) * FP + 8 * j + g]);
                mma_tf32(oacc[j], af, bf);
            }
        }
        __syncthreads();
    }

    // ---- epilogue: normalize and store ----
    float inv0 = 1.f / rl0, inv8 = 1.f / rl8;
    size_t r0 = base + (size_t)rowg0 * Dd;
    size_t r8 = base + (size_t)rowg8 * Dd;
#pragma unroll
    for (int j = 0; j < 8; j++) {
        int col = 8 * j + 2 * tg;
        float2 v0, v1;
        v0.x = oacc[j][0] * inv0; v0.y = oacc[j][1] * inv0;
        v1.x = oacc[j][2] * inv8; v1.y = oacc[j][3] * inv8;
        *(float2*)(O + r0 + col) = v0;
        *(float2*)(O + r8 + col) = v1;
    }
}

// ---------------------------------------------------------------------------
// Backward window attention (unchanged, R9/R15-validated)
// ---------------------------------------------------------------------------
__global__ __launch_bounds__(256)
void bwd_win_kernel(const float* __restrict__ Q, const float* __restrict__ K,
                    const float* __restrict__ V, float* __restrict__ O) {
    int warp = (blockIdx.x * blockDim.x + threadIdx.x) >> 5;
    int lane = threadIdx.x & 31;
    int q  = warp % Ss;
    int bh = warp / Ss;
    int h = bh % Hh, b = bh / Hh;
    size_t base = ((size_t)b * Ss) * Dd + (size_t)h * HDh;
    int d0 = lane << 1;

    if (q == Ss - 1) {
        float a0 = 0.f, a1 = 0.f;
        for (int kk = 0; kk < Ss; kk++) {
            const float* vp = V + base + (size_t)kk * Dd + d0;
            a0 += vp[0]; a1 += vp[1];
        }
        const float invS = 1.f / (float)Ss;
        *(float2*)(O + base + (size_t)q * Dd + d0) = make_float2(a0 * invS, a1 * invS);
        return;
    }

    int nk = Ss - 1 - q; if (nk > WINw) nk = WINw;
    const float* qp = Q + base + (size_t)q * Dd;
    float s = -1e30f;
    if (lane < nk) {
        const float* kp = K + base + (size_t)(q + 1 + lane) * Dd;
        float acc = 0.f;
#pragma unroll 8
        for (int d = 0; d < HDh; d++) acc += qp[d] * kp[d];
        s = acc * 0.125f;
    }
    float mx = s;
#pragma unroll
    for (int off = 16; off; off >>= 1) mx = fmaxf(mx, __shfl_xor_sync(0xffffffffu, mx, off));
    float p = (lane < nk) ? __expf(s - mx) : 0.f;
    float sum = p;
#pragma unroll
    for (int off = 16; off; off >>= 1) sum += __shfl_xor_sync(0xffffffffu, sum, off);

    float a0 = 0.f, a1 = 0.f;
    for (int j = 0; j < nk; j++) {
        float pj = __shfl_sync(0xffffffffu, p, j);
        const float* vp = V + base + (size_t)(q + 1 + j) * Dd + d0;
        a0 += pj * vp[0];
        a1 += pj * vp[1];
    }
    float inv = 1.f / sum;
    *(float2*)(O + base + (size_t)q * Dd + d0) = make_float2(a0 * inv, a1 * inv);
}

// ---------------------------------------------------------------------------
// Gate epilogue (unchanged)
// ---------------------------------------------------------------------------
__global__ void gate_fuse_kernel(const float* __restrict__ gpre, const float* __restrict__ fwd,
                                 const float* __restrict__ bwd, const float* __restrict__ gg,
                                 const float* __restrict__ gb, const float* __restrict__ bstr,
                                 float* __restrict__ fused) {
    __shared__ float red[16];
    int row = blockIdx.x;
    size_t off = (size_t)row * Dd + (threadIdx.x << 2);
    float4 v = *(const float4*)(gpre + off);
    float sum = v.x + v.y + v.z + v.w;
    float sq  = v.x * v.x + v.y * v.y + v.z * v.z + v.w * v.w;
    int lane = threadIdx.x & 31, w = threadIdx.x >> 5;
#pragma unroll
    for (int o = 16; o; o >>= 1) {
        sum += __shfl_xor_sync(0xffffffffu, sum, o);
        sq  += __shfl_xor_sync(0xffffffffu, sq,  o);
    }
    if (lane == 0) { red[w] = sum; red[8 + w] = sq; }
    __syncthreads();
    float ts = 0.f, tq = 0.f;
#pragma unroll
    for (int i = 0; i < 8; i++) { ts += red[i]; tq += red[8 + i]; }
    float mean = ts * (1.f / Dd);
    float var  = tq * (1.f / Dd) - mean * mean;
    float rstd = rsqrtf(var + 1e-5f);
    float strength = 0.3f / (1.f + __expf(-bstr[0]));

    int c = threadIdx.x << 2;
    float4 g4 = *(const float4*)(gg + c);
    float4 b4 = *(const float4*)(gb + c);
    float4 fw = *(const float4*)(fwd + off);
    float4 bw = *(const float4*)(bwd + off);
    float4 out;
    float gx;
    gx = (v.x - mean) * rstd * g4.x + b4.x; out.x = fw.x + strength * bw.x / (1.f + __expf(-gx));
    gx = (v.y - mean) * rstd * g4.y + b4.y; out.y = fw.y + strength * bw.y / (1.f + __expf(-gx));
    gx = (v.z - mean) * rstd * g4.z + b4.z; out.z = fw.z + strength * bw.z / (1.f + __expf(-gx));
    gx = (v.w - mean) * rstd * g4.w + b4.w; out.w = fw.w + strength * bw.w / (1.f + __expf(-gx));
    *(float4*)(fused + off) = out;
}

// ---------------------------------------------------------------------------
// Final LN (unchanged)
// ---------------------------------------------------------------------------
__global__ void final_ln_kernel(const float* __restrict__ x, const float* __restrict__ o,
                                const float* __restrict__ gg, const float* __restrict__ gb,
                                float* __restrict__ y) {
    __shared__ float red[16];
    int row = blockIdx.x;
    size_t off = (size_t)row * Dd + (threadIdx.x << 2);
    float4 a = *(const float4*)(x + off);
    float4 c4 = *(const float4*)(o + off);
    float4 v;
    v.x = a.x + c4.x; v.y = a.y + c4.y; v.z = a.z + c4.z; v.w = a.w + c4.w;
    float sum = v.x + v.y + v.z + v.w;
    float sq  = v.x * v.x + v.y * v.y + v.z * v.z + v.w * v.w;
    int lane = threadIdx.x & 31, w = threadIdx.x >> 5;
#pragma unroll
    for (int oo = 16; oo; oo >>= 1) {
        sum += __shfl_xor_sync(0xffffffffu, sum, oo);
        sq  += __shfl_xor_sync(0xffffffffu, sq,  oo);
    }
    if (lane == 0) { red[w] = sum; red[8 + w] = sq; }
    __syncthreads();
    float ts = 0.f, tq = 0.f;
#pragma unroll
    for (int i = 0; i < 8; i++) { ts += red[i]; tq += red[8 + i]; }
    float mean = ts * (1.f / Dd);
    float var  = tq * (1.f / Dd) - mean * mean;
    float rstd = rsqrtf(var + 1e-5f);

    int c = threadIdx.x << 2;
    float4 g4 = *(const float4*)(gg + c);
    float4 b4 = *(const float4*)(gb + c);
    float4 out;
    out.x = (v.x - mean) * rstd * g4.x + b4.x;
    out.y = (v.y - mean) * rstd * g4.y + b4.y;
    out.z = (v.z - mean) * rstd * g4.z + b4.z;
    out.w = (v.w - mean) * rstd * g4.w + b4.w;
    *(float4*)(y + off) = out;
}

// ---------------------------------------------------------------------------
// Launch
// ---------------------------------------------------------------------------
extern "C" void kernel_launch(void* const* d_in, const int* in_sizes, int n_in,
                              void* d_out, int out_size) {
    const float* x      = (const float*)d_in[0];
    const float* fq_w   = (const float*)d_in[1];
    const float* fq_b   = (const float*)d_in[2];
    const float* fk_w   = (const float*)d_in[3];
    const float* fk_b   = (const float*)d_in[4];
    const float* fv_w   = (const float*)d_in[5];
    const float* fv_b   = (const float*)d_in[6];
    const float* bq_w   = (const float*)d_in[7];
    const float* bq_b   = (const float*)d_in[8];
    const float* bk_w   = (const float*)d_in[9];
    const float* bk_b   = (const float*)d_in[10];
    const float* bv_w   = (const float*)d_in[11];
    const float* bv_b   = (const float*)d_in[12];
    const float* gate_w = (const float*)d_in[13];
    const float* gate_b = (const float*)d_in[14];
    const float* gln_g  = (const float*)d_in[15];
    const float* gln_b  = (const float*)d_in[16];
    const float* bstr   = (const float*)d_in[17];
    const float* out_w  = (const float*)d_in[18];
    const float* out_b  = (const float*)d_in[19];
    const float* ln_g   = (const float*)d_in[20];
    const float* ln_b   = (const float*)d_in[21];

    float* s0 = nullptr;
    cudaGetSymbolAddress((void**)&s0, g_scratch);
    const size_t T = (size_t)Mrows * Dd;
    float* q    = s0;
    float* k    = s0 + 1 * T;
    float* v    = s0 + 2 * T;
    float* qb   = s0 + 3 * T;
    float* kb   = s0 + 4 * T;
    float* vb   = s0 + 5 * T;
    float* fwd  = s0 + 6 * T;
    float* bwd  = s0 + 7 * T;
    float* gate = s0 + 8 * T;
    float* fus  = s0 + 9 * T;
    float* ob   = s0 + 10 * T;

    cudaFuncSetAttribute(flash_fwd_kernel,
                         cudaFuncAttributeMaxDynamicSharedMemorySize, FLASH_SMEM);

    QkvArgs qa;
    qa.W[0] = fq_w; qa.bias[0] = fq_b; qa.out[0] = q;
    qa.W[1] = fk_w; qa.bias[1] = fk_b; qa.out[1] = k;
    qa.W[2] = fv_w; qa.bias[2] = fv_b; qa.out[2] = v;
    qa.W[3] = bq_w; qa.bias[3] = bq_b; qa.out[3] = qb;
    qa.W[4] = bk_w; qa.bias[4] = bk_b; qa.out[4] = kb;
    qa.W[5] = bv_w; qa.bias[5] = bv_b; qa.out[5] = vb;
    qkv_sgemm_kernel<<<dim3(Dd / BN, Mrows / BM, 6), 256>>>(x, qa);

    flash_fwd_kernel<<<dim3(Ss / 64, Hh, Bb), 128, FLASH_SMEM>>>(q, k, v, fwd);
    bwd_win_kernel<<<(Bb * Hh * Ss) / 8, 256>>>(qb, kb, vb, bwd);

    dim3 gg(Dd / BN, Mrows / BM);

    sgemm_kernel<<<gg, 256>>>(fwd, bwd, Dd, gate_w, gate_b, gate, Dd, 2 * Dd);

    gate_fuse_kernel<<<Mrows, 256>>>(gate, fwd, bwd, gln_g, gln_b, bstr, fus);

    sgemm_kernel<<<gg, 256>>>(fus, fus, Dd, out_w, out_b, ob, Dd, Dd);

    final_ln_kernel<<<Mrows, 256>>>(x, ob, ln_g, ln_b, (float*)d_out);
}

// round 17
// speedup vs baseline: 3.5018x; 1.0315x over previous
#include <cuda_runtime.h>
#include <math.h>
#include <stdint.h>

#define Bb   2
#define Ss   2048
#define Dd   1024
#define Hh   16
#define HDh  64
#define WINw 32
#define Mrows 4096   // B*S

__device__ float g_scratch[11ull * 4194304ull];

#define BM 128
#define BN 128
#define BKt 16
#define AST 136
#define BST 136

// ---------------------------------------------------------------------------
// tf32 helpers (fragment layouts hardware-validated in R15/R16)
// ---------------------------------------------------------------------------
__device__ __forceinline__ float f2tf32f(float f) {
    uint32_t u;
    asm("cvt.rna.tf32.f32 %0, %1;" : "=r"(u) : "f"(f));
    return __uint_as_float(u);
}

__device__ __forceinline__ void mma_tf32(float* d, const uint32_t* a, const uint32_t* b) {
    asm volatile(
        "mma.sync.aligned.m16n8k8.row.col.f32.tf32.tf32.f32 "
        "{%0,%1,%2,%3}, {%4,%5,%6,%7}, {%8,%9}, {%0,%1,%2,%3};\n"
        : "+f"(d[0]), "+f"(d[1]), "+f"(d[2]), "+f"(d[3])
        : "r"(a[0]), "r"(a[1]), "r"(a[2]), "r"(a[3]), "r"(b[0]), "r"(b[1]));
}

// ---------------------------------------------------------------------------
// tf32 GEMM body (R15-validated)
// ---------------------------------------------------------------------------
__device__ __forceinline__
void tf32_gemm_body(const float* __restrict__ A1, const float* __restrict__ A2,
                    int K1, const float* __restrict__ W,
                    const float* __restrict__ bias, float* __restrict__ C,
                    int N, int K, int row0, int col0,
                    float As[2][BKt][AST], float Bs[2][BKt][BST]) {
    const int tid    = threadIdx.x;
    const int lane   = tid & 31;
    const int wid    = tid >> 5;
    const int warp_m = wid >> 2;
    const int warp_n = wid & 3;
    const int g      = lane >> 2;
    const int tg     = lane & 3;
    const int wm     = warp_m * 64;
    const int wn     = warp_n * 32;

    const int ar0 = tid >> 2;
    const int ac0 = (tid & 3) << 2;
    const int br0 = tid >> 5;
    const int bc0 = (tid & 31) << 2;

    float acc[4][4][4];
#pragma unroll
    for (int i = 0; i < 4; i++)
#pragma unroll
        for (int j = 0; j < 4; j++)
#pragma unroll
            for (int t = 0; t < 4; t++) acc[i][j][t] = 0.f;

#pragma unroll
    for (int i = 0; i < 2; i++) {
        int r = ar0 + i * 64;
        float4 v = *(const float4*)(A1 + (size_t)(row0 + r) * K1 + ac0);
        As[0][ac0 + 0][r] = f2tf32f(v.x);
        As[0][ac0 + 1][r] = f2tf32f(v.y);
        As[0][ac0 + 2][r] = f2tf32f(v.z);
        As[0][ac0 + 3][r] = f2tf32f(v.w);
    }
#pragma unroll
    for (int i = 0; i < 2; i++) {
        int r = br0 + i * 8;
        float4 v = *(const float4*)(W + (size_t)r * N + col0 + bc0);
        Bs[0][r][bc0 + 0] = f2tf32f(v.x);
        Bs[0][r][bc0 + 1] = f2tf32f(v.y);
        Bs[0][r][bc0 + 2] = f2tf32f(v.z);
        Bs[0][r][bc0 + 3] = f2tf32f(v.w);
    }
    __syncthreads();

    int cur = 0;
    for (int k0 = 0; k0 < K; k0 += BKt) {
        const int knext = k0 + BKt;
        float4 apre[2], bpre[2];
        if (knext < K) {
            const float* Asrc = (knext < K1) ? A1 : A2;
            const int    kc   = (knext < K1) ? knext : (knext - K1);
            const int    Ka   = (K1 < K) ? K1 : K;
#pragma unroll
            for (int i = 0; i < 2; i++) {
                int r = ar0 + i * 64;
                apre[i] = *(const float4*)(Asrc + (size_t)(row0 + r) * Ka + kc + ac0);
            }
#pragma unroll
            for (int i = 0; i < 2; i++) {
                int r = br0 + i * 8;
                bpre[i] = *(const float4*)(W + (size_t)(knext + r) * N + col0 + bc0);
            }
        }

#pragma unroll
        for (int ks = 0; ks < 2; ks++) {
            const int kb = ks * 8;
            uint32_t afr[4][4], bfr[4][2];
#pragma unroll
            for (int i = 0; i < 4; i++) {
                const int mb = wm + i * 16;
                afr[i][0] = __float_as_uint(As[cur][kb + tg    ][mb + g    ]);
                afr[i][1] = __float_as_uint(As[cur][kb + tg    ][mb + g + 8]);
                afr[i][2] = __float_as_uint(As[cur][kb + tg + 4][mb + g    ]);
                afr[i][3] = __float_as_uint(As[cur][kb + tg + 4][mb + g + 8]);
            }
#pragma unroll
            for (int j = 0; j < 4; j++) {
                const int nb = wn + j * 8;
                bfr[j][0] = __float_as_uint(Bs[cur][kb + tg    ][nb + g]);
                bfr[j][1] = __float_as_uint(Bs[cur][kb + tg + 4][nb + g]);
            }
#pragma unroll
            for (int i = 0; i < 4; i++)
#pragma unroll
                for (int j = 0; j < 4; j++)
                    mma_tf32(acc[i][j], afr[i], bfr[j]);
        }

        if (knext < K) {
            const int nxt = cur ^ 1;
#pragma unroll
            for (int i = 0; i < 2; i++) {
                int r = ar0 + i * 64;
                As[nxt][ac0 + 0][r] = f2tf32f(apre[i].x);
                As[nxt][ac0 + 1][r] = f2tf32f(apre[i].y);
                As[nxt][ac0 + 2][r] = f2tf32f(apre[i].z);
                As[nxt][ac0 + 3][r] = f2tf32f(apre[i].w);
            }
#pragma unroll
            for (int i = 0; i < 2; i++) {
                int r = br0 + i * 8;
                Bs[nxt][r][bc0 + 0] = f2tf32f(bpre[i].x);
                Bs[nxt][r][bc0 + 1] = f2tf32f(bpre[i].y);
                Bs[nxt][r][bc0 + 2] = f2tf32f(bpre[i].z);
                Bs[nxt][r][bc0 + 3] = f2tf32f(bpre[i].w);
            }
            __syncthreads();
            cur = nxt;
        }
    }

#pragma unroll
    for (int i = 0; i < 4; i++) {
        const int mrow = row0 + wm + i * 16 + g;
#pragma unroll
        for (int j = 0; j < 4; j++) {
            const int col = col0 + wn + j * 8 + tg * 2;
            float b0v = 0.f, b1v = 0.f;
            if (bias) { b0v = bias[col]; b1v = bias[col + 1]; }
            float2 v0, v1;
            v0.x = acc[i][j][0] + b0v; v0.y = acc[i][j][1] + b1v;
            v1.x = acc[i][j][2] + b0v; v1.y = acc[i][j][3] + b1v;
            *(float2*)(C + (size_t)mrow * N + col)       = v0;
            *(float2*)(C + (size_t)(mrow + 8) * N + col) = v1;
        }
    }
}

struct QkvArgs {
    const float* W[6];
    const float* bias[6];
    float*       out[6];
};

__global__ __launch_bounds__(256, 2)
void qkv_sgemm_kernel(const float* __restrict__ A, QkvArgs args) {
    __shared__ float As[2][BKt][AST];
    __shared__ float Bs[2][BKt][BST];
    const int z = blockIdx.z;
    tf32_gemm_body(A, A, Dd, args.W[z], args.bias[z], args.out[z],
                   Dd, Dd, blockIdx.y * BM, blockIdx.x * BN, As, Bs);
}

__global__ __launch_bounds__(256, 2)
void sgemm_kernel(const float* __restrict__ A1, const float* __restrict__ A2,
                  int K1, const float* __restrict__ W,
                  const float* __restrict__ bias, float* __restrict__ C,
                  int N, int K) {
    __shared__ float As[2][BKt][AST];
    __shared__ float Bs[2][BKt][BST];
    tf32_gemm_body(A1, A2, K1, W, bias, C, N, K,
                   blockIdx.y * BM, blockIdx.x * BN, As, Bs);
}

// ---------------------------------------------------------------------------
// Flash-attention forward (causal) with tf32 mma -- R16-validated, unchanged
// ---------------------------------------------------------------------------
#define FP 72
#define FLASH_SMEM (3 * 64 * FP * 4)

__global__ void flash_fwd_kernel(const float* __restrict__ Q, const float* __restrict__ K,
                                 const float* __restrict__ V, float* __restrict__ O) {
    extern __shared__ float sm[];
    float* Qs = sm;                 // [d][q]   64 x FP
    float* Kt = sm + 64 * FP;       // [d][key] 64 x FP
    float* Vs = sm + 2 * 64 * FP;   // [key][d] 64 x FP

    const int tid  = threadIdx.x;
    const int lane = tid & 31;
    const int w    = tid >> 5;
    const int g    = lane >> 2;
    const int tg   = lane & 3;
    const int quad = lane & ~3;
    const int wm   = w * 16;

    const int qt = gridDim.x - 1 - blockIdx.x;
    const int h  = blockIdx.y;
    const int b  = blockIdx.z;
    const size_t base = ((size_t)b * Ss) * Dd + (size_t)h * HDh;

#pragma unroll
    for (int i = 0; i < 8; i++) {
        int f  = tid + i * 128;
        int rr = f >> 4;
        int cc = (f & 15) << 2;
        float4 v = *(const float4*)(Q + base + (size_t)(qt * 64 + rr) * Dd + cc);
        Qs[(cc + 0) * FP + rr] = f2tf32f(v.x);
        Qs[(cc + 1) * FP + rr] = f2tf32f(v.y);
        Qs[(cc + 2) * FP + rr] = f2tf32f(v.z);
        Qs[(cc + 3) * FP + rr] = f2tf32f(v.w);
    }
    __syncthreads();

    uint32_t qf[8][4];
#pragma unroll
    for (int kd = 0; kd < 8; kd++) {
        qf[kd][0] = __float_as_uint(Qs[(8 * kd + tg    ) * FP + wm + g    ]);
        qf[kd][1] = __float_as_uint(Qs[(8 * kd + tg    ) * FP + wm + g + 8]);
        qf[kd][2] = __float_as_uint(Qs[(8 * kd + tg + 4) * FP + wm + g    ]);
        qf[kd][3] = __float_as_uint(Qs[(8 * kd + tg + 4) * FP + wm + g + 8]);
    }

    const int   rowg0 = qt * 64 + wm + g;
    const int   rowg8 = rowg0 + 8;
    const float scale = 0.125f;

    float rm0 = -1e30f, rm8 = -1e30f, rl0 = 0.f, rl8 = 0.f;
    float oacc[8][4];
#pragma unroll
    for (int j = 0; j < 8; j++)
#pragma unroll
        for (int t = 0; t < 4; t++) oacc[j][t] = 0.f;

    for (int kt = 0; kt <= qt; kt++) {
#pragma unroll
        for (int i = 0; i < 8; i++) {
            int f  = tid + i * 128;
            int rr = f >> 4;
            int cc = (f & 15) << 2;
            size_t gaddr = base + (size_t)(kt * 64 + rr) * Dd + cc;
            float4 kv = *(const float4*)(K + gaddr);
            Kt[(cc + 0) * FP + rr] = f2tf32f(kv.x);
            Kt[(cc + 1) * FP + rr] = f2tf32f(kv.y);
            Kt[(cc + 2) * FP + rr] = f2tf32f(kv.z);
            Kt[(cc + 3) * FP + rr] = f2tf32f(kv.w);
            float4 vv = *(const float4*)(V + gaddr);
            float4 vr;
            vr.x = f2tf32f(vv.x); vr.y = f2tf32f(vv.y);
            vr.z = f2tf32f(vv.z); vr.w = f2tf32f(vv.w);
            *(float4*)(Vs + rr * FP + cc) = vr;
        }
        __syncthreads();

        float sacc[8][4];
#pragma unroll
        for (int j = 0; j < 8; j++)
#pragma unroll
            for (int t = 0; t < 4; t++) sacc[j][t] = 0.f;
#pragma unroll
        for (int kd = 0; kd < 8; kd++) {
#pragma unroll
            for (int j = 0; j < 8; j++) {
                uint32_t bf[2];
                bf[0] = __float_as_uint(Kt[(8 * kd + tg    ) * FP + 8 * j + g]);
                bf[1] = __float_as_uint(Kt[(8 * kd + tg + 4) * FP + 8 * j + g]);
                mma_tf32(sacc[j], qf[kd], bf);
            }
        }

        const bool diag = (kt == qt);
#pragma unroll
        for (int j = 0; j < 8; j++) {
            int col = kt * 64 + 8 * j + 2 * tg;
            sacc[j][0] *= scale; sacc[j][1] *= scale;
            sacc[j][2] *= scale; sacc[j][3] *= scale;
            if (diag) {
                if (col     > rowg0) sacc[j][0] = -1e30f;
                if (col + 1 > rowg0) sacc[j][1] = -1e30f;
                if (col     > rowg8) sacc[j][2] = -1e30f;
                if (col + 1 > rowg8) sacc[j][3] = -1e30f;
            }
        }

        float mx0 = -1e30f, mx8 = -1e30f;
#pragma unroll
        for (int j = 0; j < 8; j++) {
            mx0 = fmaxf(mx0, fmaxf(sacc[j][0], sacc[j][1]));
            mx8 = fmaxf(mx8, fmaxf(sacc[j][2], sacc[j][3]));
        }
        mx0 = fmaxf(mx0, __shfl_xor_sync(0xffffffffu, mx0, 1));
        mx0 = fmaxf(mx0, __shfl_xor_sync(0xffffffffu, mx0, 2));
        mx8 = fmaxf(mx8, __shfl_xor_sync(0xffffffffu, mx8, 1));
        mx8 = fmaxf(mx8, __shfl_xor_sync(0xffffffffu, mx8, 2));

        float mnew0 = fmaxf(rm0, mx0), mnew8 = fmaxf(rm8, mx8);
        float corr0 = __expf(rm0 - mnew0), corr8 = __expf(rm8 - mnew8);

        float sum0 = 0.f, sum8 = 0.f;
#pragma unroll
        for (int j = 0; j < 8; j++) {
            sacc[j][0] = __expf(sacc[j][0] - mnew0);
            sacc[j][1] = __expf(sacc[j][1] - mnew0);
            sacc[j][2] = __expf(sacc[j][2] - mnew8);
            sacc[j][3] = __expf(sacc[j][3] - mnew8);
            sum0 += sacc[j][0] + sacc[j][1];
            sum8 += sacc[j][2] + sacc[j][3];
        }
        sum0 += __shfl_xor_sync(0xffffffffu, sum0, 1);
        sum0 += __shfl_xor_sync(0xffffffffu, sum0, 2);
        sum8 += __shfl_xor_sync(0xffffffffu, sum8, 1);
        sum8 += __shfl_xor_sync(0xffffffffu, sum8, 2);

        rl0 = rl0 * corr0 + sum0;  rm0 = mnew0;
        rl8 = rl8 * corr8 + sum8;  rm8 = mnew8;
#pragma unroll
        for (int j = 0; j < 8; j++) {
            oacc[j][0] *= corr0; oacc[j][1] *= corr0;
            oacc[j][2] *= corr8; oacc[j][3] *= corr8;
        }

#pragma unroll
        for (int ks = 0; ks < 8; ks++) {
            const int srcA = quad + (tg >> 1);
            const int srcB = srcA + 2;
            float p0 = __shfl_sync(0xffffffffu, sacc[ks][0], srcA);
            float p1 = __shfl_sync(0xffffffffu, sacc[ks][1], srcA);
            float p2 = __shfl_sync(0xffffffffu, sacc[ks][2], srcA);
            float p3 = __shfl_sync(0xffffffffu, sacc[ks][3], srcA);
            float q0 = __shfl_sync(0xffffffffu, sacc[ks][0], srcB);
            float q1 = __shfl_sync(0xffffffffu, sacc[ks][1], srcB);
            float q2 = __shfl_sync(0xffffffffu, sacc[ks][2], srcB);
            float q3 = __shfl_sync(0xffffffffu, sacc[ks][3], srcB);
            uint32_t af[4];
            af[0] = __float_as_uint(f2tf32f((tg & 1) ? p1 : p0));
            af[1] = __float_as_uint(f2tf32f((tg & 1) ? p3 : p2));
            af[2] = __float_as_uint(f2tf32f((tg & 1) ? q1 : q0));
            af[3] = __float_as_uint(f2tf32f((tg & 1) ? q3 : q2));
#pragma unroll
            for (int j = 0; j < 8; j++) {
                uint32_t bf[2];
                bf[0] = __float_as_uint(Vs[(8 * ks + tg    ) * FP + 8 * j + g]);
                bf[1] = __float_as_uint(Vs[(8 * ks + tg + 4) * FP + 8 * j + g]);
                mma_tf32(oacc[j], af, bf);
            }
        }
        __syncthreads();
    }

    float inv0 = 1.f / rl0, inv8 = 1.f / rl8;
    size_t r0 = base + (size_t)rowg0 * Dd;
    size_t r8 = base + (size_t)rowg8 * Dd;
#pragma unroll
    for (int j = 0; j < 8; j++) {
        int col = 8 * j + 2 * tg;
        float2 v0, v1;
        v0.x = oacc[j][0] * inv0; v0.y = oacc[j][1] * inv0;
        v1.x = oacc[j][2] * inv8; v1.y = oacc[j][3] * inv8;
        *(float2*)(O + r0 + col) = v0;
        *(float2*)(O + r8 + col) = v1;
    }
}

// ---------------------------------------------------------------------------
// mean_v_kernel: bwd row q=S-1 (all-masked -> uniform softmax over full S)
// = column mean of Vb per (b,h). One 256-thread block per (b,h):
// thread (part=tid>>6, d=tid&63) sums 512 rows, smem-reduce 4 parts.
// ---------------------------------------------------------------------------
__global__ void mean_v_kernel(const float* __restrict__ V, float* __restrict__ O) {
    __shared__ float red[256];
    const int bh = blockIdx.x;
    const int h = bh % Hh, b = bh / Hh;
    const size_t base = ((size_t)b * Ss) * Dd + (size_t)h * HDh;
    const int d    = threadIdx.x & 63;
    const int part = threadIdx.x >> 6;     // 0..3
    float acc = 0.f;
    for (int kk = part * 512; kk < (part + 1) * 512; kk++)
        acc += V[base + (size_t)kk * Dd + d];
    red[threadIdx.x] = acc;
    __syncthreads();
    if (part == 0) {
        float s = red[d] + red[64 + d] + red[128 + d] + red[192 + d];
        O[base + (size_t)(Ss - 1) * Dd + d] = s * (1.f / (float)Ss);
    }
}

// ---------------------------------------------------------------------------
// Backward window attention (q=S-1 handled by mean_v_kernel)
// ---------------------------------------------------------------------------
__global__ __launch_bounds__(256)
void bwd_win_kernel(const float* __restrict__ Q, const float* __restrict__ K,
                    const float* __restrict__ V, float* __restrict__ O) {
    int warp = (blockIdx.x * blockDim.x + threadIdx.x) >> 5;
    int lane = threadIdx.x & 31;
    int q  = warp % Ss;
    int bh = warp / Ss;
    int h = bh % Hh, b = bh / Hh;
    size_t base = ((size_t)b * Ss) * Dd + (size_t)h * HDh;
    int d0 = lane << 1;

    if (q == Ss - 1) return;   // handled by mean_v_kernel

    int nk = Ss - 1 - q; if (nk > WINw) nk = WINw;
    const float* qp = Q + base + (size_t)q * Dd;
    float s = -1e30f;
    if (lane < nk) {
        const float* kp = K + base + (size_t)(q + 1 + lane) * Dd;
        float acc = 0.f;
#pragma unroll 8
        for (int d = 0; d < HDh; d++) acc += qp[d] * kp[d];
        s = acc * 0.125f;
    }
    float mx = s;
#pragma unroll
    for (int off = 16; off; off >>= 1) mx = fmaxf(mx, __shfl_xor_sync(0xffffffffu, mx, off));
    float p = (lane < nk) ? __expf(s - mx) : 0.f;
    float sum = p;
#pragma unroll
    for (int off = 16; off; off >>= 1) sum += __shfl_xor_sync(0xffffffffu, sum, off);

    float a0 = 0.f, a1 = 0.f;
    for (int j = 0; j < nk; j++) {
        float pj = __shfl_sync(0xffffffffu, p, j);
        const float* vp = V + base + (size_t)(q + 1 + j) * Dd + d0;
        a0 += pj * vp[0];
        a1 += pj * vp[1];
    }
    float inv = 1.f / sum;
    *(float2*)(O + base + (size_t)q * Dd + d0) = make_float2(a0 * inv, a1 * inv);
}

// ---------------------------------------------------------------------------
// Gate epilogue (unchanged)
// ---------------------------------------------------------------------------
__global__ void gate_fuse_kernel(const float* __restrict__ gpre, const float* __restrict__ fwd,
                                 const float* __restrict__ bwd, const float* __restrict__ gg,
                                 const float* __restrict__ gb, const float* __restrict__ bstr,
                                 float* __restrict__ fused) {
    __shared__ float red[16];
    int row = blockIdx.x;
    size_t off = (size_t)row * Dd + (threadIdx.x << 2);
    float4 v = *(const float4*)(gpre + off);
    float sum = v.x + v.y + v.z + v.w;
    float sq  = v.x * v.x + v.y * v.y + v.z * v.z + v.w * v.w;
    int lane = threadIdx.x & 31, w = threadIdx.x >> 5;
#pragma unroll
    for (int o = 16; o; o >>= 1) {
        sum += __shfl_xor_sync(0xffffffffu, sum, o);
        sq  += __shfl_xor_sync(0xffffffffu, sq,  o);
    }
    if (lane == 0) { red[w] = sum; red[8 + w] = sq; }
    __syncthreads();
    float ts = 0.f, tq = 0.f;
#pragma unroll
    for (int i = 0; i < 8; i++) { ts += red[i]; tq += red[8 + i]; }
    float mean = ts * (1.f / Dd);
    float var  = tq * (1.f / Dd) - mean * mean;
    float rstd = rsqrtf(var + 1e-5f);
    float strength = 0.3f / (1.f + __expf(-bstr[0]));

    int c = threadIdx.x << 2;
    float4 g4 = *(const float4*)(gg + c);
    float4 b4 = *(const float4*)(gb + c);
    float4 fw = *(const float4*)(fwd + off);
    float4 bw = *(const float4*)(bwd + off);
    float4 out;
    float gx;
    gx = (v.x - mean) * rstd * g4.x + b4.x; out.x = fw.x + strength * bw.x / (1.f + __expf(-gx));
    gx = (v.y - mean) * rstd * g4.y + b4.y; out.y = fw.y + strength * bw.y / (1.f + __expf(-gx));
    gx = (v.z - mean) * rstd * g4.z + b4.z; out.z = fw.z + strength * bw.z / (1.f + __expf(-gx));
    gx = (v.w - mean) * rstd * g4.w + b4.w; out.w = fw.w + strength * bw.w / (1.f + __expf(-gx));
    *(float4*)(fused + off) = out;
}

// ---------------------------------------------------------------------------
// Final LN (unchanged)
// ---------------------------------------------------------------------------
__global__ void final_ln_kernel(const float* __restrict__ x, const float* __restrict__ o,
                                const float* __restrict__ gg, const float* __restrict__ gb,
                                float* __restrict__ y) {
    __shared__ float red[16];
    int row = blockIdx.x;
    size_t off = (size_t)row * Dd + (threadIdx.x << 2);
    float4 a = *(const float4*)(x + off);
    float4 c4 = *(const float4*)(o + off);
    float4 v;
    v.x = a.x + c4.x; v.y = a.y + c4.y; v.z = a.z + c4.z; v.w = a.w + c4.w;
    float sum = v.x + v.y + v.z + v.w;
    float sq  = v.x * v.x + v.y * v.y + v.z * v.z + v.w * v.w;
    int lane = threadIdx.x & 31, w = threadIdx.x >> 5;
#pragma unroll
    for (int oo = 16; oo; oo >>= 1) {
        sum += __shfl_xor_sync(0xffffffffu, sum, oo);
        sq  += __shfl_xor_sync(0xffffffffu, sq,  oo);
    }
    if (lane == 0) { red[w] = sum; red[8 + w] = sq; }
    __syncthreads();
    float ts = 0.f, tq = 0.f;
#pragma unroll
    for (int i = 0; i < 8; i++) { ts += red[i]; tq += red[8 + i]; }
    float mean = ts * (1.f / Dd);
    float var  = tq * (1.f / Dd) - mean * mean;
    float rstd = rsqrtf(var + 1e-5f);

    int c = threadIdx.x << 2;
    float4 g4 = *(const float4*)(gg + c);
    float4 b4 = *(const float4*)(gb + c);
    float4 out;
    out.x = (v.x - mean) * rstd * g4.x + b4.x;
    out.y = (v.y - mean) * rstd * g4.y + b4.y;
    out.z = (v.z - mean) * rstd * g4.z + b4.z;
    out.w = (v.w - mean) * rstd * g4.w + b4.w;
    *(float4*)(y + off) = out;
}

// ---------------------------------------------------------------------------
// Launch
// ---------------------------------------------------------------------------
extern "C" void kernel_launch(void* const* d_in, const int* in_sizes, int n_in,
                              void* d_out, int out_size) {
    const float* x      = (const float*)d_in[0];
    const float* fq_w   = (const float*)d_in[1];
    const float* fq_b   = (const float*)d_in[2];
    const float* fk_w   = (const float*)d_in[3];
    const float* fk_b   = (const float*)d_in[4];
    const float* fv_w   = (const float*)d_in[5];
    const float* fv_b   = (const float*)d_in[6];
    const float* bq_w   = (const float*)d_in[7];
    const float* bq_b   = (const float*)d_in[8];
    const float* bk_w   = (const float*)d_in[9];
    const float* bk_b   = (const float*)d_in[10];
    const float* bv_w   = (const float*)d_in[11];
    const float* bv_b   = (const float*)d_in[12];
    const float* gate_w = (const float*)d_in[13];
    const float* gate_b = (const float*)d_in[14];
    const float* gln_g  = (const float*)d_in[15];
    const float* gln_b  = (const float*)d_in[16];
    const float* bstr   = (const float*)d_in[17];
    const float* out_w  = (const float*)d_in[18];
    const float* out_b  = (const float*)d_in[19];
    const float* ln_g   = (const float*)d_in[20];
    const float* ln_b   = (const float*)d_in[21];

    float* s0 = nullptr;
    cudaGetSymbolAddress((void**)&s0, g_scratch);
    const size_t T = (size_t)Mrows * Dd;
    float* q    = s0;
    float* k    = s0 + 1 * T;
    float* v    = s0 + 2 * T;
    float* qb   = s0 + 3 * T;
    float* kb   = s0 + 4 * T;
    float* vb   = s0 + 5 * T;
    float* fwd  = s0 + 6 * T;
    float* bwd  = s0 + 7 * T;
    float* gate = s0 + 8 * T;
    float* fus  = s0 + 9 * T;
    float* ob   = s0 + 10 * T;

    cudaFuncSetAttribute(flash_fwd_kernel,
                         cudaFuncAttributeMaxDynamicSharedMemorySize, FLASH_SMEM);

    QkvArgs qa;
    qa.W[0] = fq_w; qa.bias[0] = fq_b; qa.out[0] = q;
    qa.W[1] = fk_w; qa.bias[1] = fk_b; qa.out[1] = k;
    qa.W[2] = fv_w; qa.bias[2] = fv_b; qa.out[2] = v;
    qa.W[3] = bq_w; qa.bias[3] = bq_b; qa.out[3] = qb;
    qa.W[4] = bk_w; qa.bias[4] = bk_b; qa.out[4] = kb;
    qa.W[5] = bv_w; qa.bias[5] = bv_b; qa.out[5] = vb;
    qkv_sgemm_kernel<<<dim3(Dd / BN, Mrows / BM, 6), 256>>>(x, qa);

    flash_fwd_kernel<<<dim3(Ss / 64, Hh, Bb), 128, FLASH_SMEM>>>(q, k, v, fwd);
    bwd_win_kernel<<<(Bb * Hh * Ss) / 8, 256>>>(qb, kb, vb, bwd);
    mean_v_kernel<<<Bb * Hh, 256>>>(vb, bwd);

    dim3 gg(Dd / BN, Mrows / BM);

    sgemm_kernel<<<gg, 256>>>(fwd, bwd, Dd, gate_w, gate_b, gate, Dd, 2 * Dd);

    gate_fuse_kernel<<<Mrows, 256>>>(gate, fwd, bwd, gln_g, gln_b, bstr, fus);

    sgemm_kernel<<<gg, 256>>>(fus, fus, Dd, out_w, out_b, ob, Dd, Dd);

    final_ln_kernel<<<Mrows, 256>>>(x, ob, ln_g, ln_b, (float*)d_out);
}